// round 2
// baseline (speedup 1.0000x reference)
#include <cuda_runtime.h>

#define BB   4
#define NN   8192
#define CCH  64
#define NPTS (BB*NN)          // 32768
#define KLn  12
#define EPSbn 1e-5f
#define G_STAT 1024
#define G_CONV 1184

// ---------------- scratch (static device arrays; no allocation) ----------------
__device__ __align__(16) float  g_xt[NPTS*CCH];            // x transposed (B,N,C)   8MB
__device__ __align__(16) float4 g_pp[NPTS];                // packed points (x,y,z,|p|^2)
__device__             int    g_idx[NPTS*KLn];             // 12 NN per point (sorted)
__device__ __align__(16) float g_PQ[4][NPTS*CCH];          // P_s,Q_s,P_l,Q_l        32MB
__device__ __align__(16) float g_h2[NPTS*KLn*CCH];         // conv2 out scratch     100MB
__device__             float  g_part[2048*128];            // block partial stats
__device__             float  g_bnA[128];                  // layer1 scale/shift
__device__             float  g_bnB[128];                  // layer2 scale/shift
__device__ __align__(16) float g_Wf[4][4096];              // folded conv1 W, [k][o]
__device__ __align__(16) float g_W2t[2][4096];             // conv2 W transposed [k][o]

// ---------------- weight prep: fold conv1, transpose everything ----------------
__global__ void k_prep(const float* __restrict__ Ws1, const float* __restrict__ Wl1,
                       const float* __restrict__ Ws2, const float* __restrict__ Wl2)
{
    int t = blockIdx.x*blockDim.x + threadIdx.x;
    if (t < 4096) {
        int o = t >> 6, c = t & 63;
        float a0 = Ws1[o*128 + c],  a1 = Ws1[o*128 + 64 + c];
        g_Wf[0][c*64+o] = a0 - a1;          // Wa_s
        g_Wf[1][c*64+o] = a1;               // Wb_s
        float b0 = Wl1[o*128 + c],  b1 = Wl1[o*128 + 64 + c];
        g_Wf[2][c*64+o] = b0 - b1;          // Wa_l
        g_Wf[3][c*64+o] = b1;               // Wb_l
        g_W2t[0][c*64+o] = Ws2[o*64+c];
        g_W2t[1][c*64+o] = Wl2[o*64+c];
    }
}

// ---------------- pack: transpose x, build float4 points ----------------
__global__ void k_pack(const float* __restrict__ x, const float* __restrict__ pos)
{
    int t = blockIdx.x*blockDim.x + threadIdx.x;
    if (t < NPTS*CCH) {
        int c = t & 63, bn = t >> 6;
        int n = bn & (NN-1), b = bn >> 13;
        g_xt[t] = x[(b*CCH + c)*NN + n];
    }
    if (t < NPTS) {
        int n = t & (NN-1), b = t >> 13;
        float px = pos[(b*3+0)*NN + n];
        float py = pos[(b*3+1)*NN + n];
        float pz = pos[(b*3+2)*NN + n];
        g_pp[t] = make_float4(px, py, pz, px*px + py*py + pz*pz);
    }
}

// ---------------- brute-force KNN: sorted top-13 (incl. self), emit 12 ----------------
#define KNN_TC 2048
__global__ __launch_bounds__(128) void k_knn()
{
    __shared__ __align__(16) float4 tile[KNN_TC];
    int b = blockIdx.y;
    int n = blockIdx.x * 128 + threadIdx.x;
    float4 q = g_pp[b*NN + n];
    float qx = -2.f*q.x, qy = -2.f*q.y, qz = -2.f*q.z;

    float bd[13]; int bi[13];
#pragma unroll
    for (int i = 0; i < 13; i++) { bd[i] = 3.4e38f; bi[i] = 0; }
    float thr = 3.4e38f;

    for (int tb = 0; tb < NN; tb += KNN_TC) {
        __syncthreads();
        for (int i = threadIdx.x; i < KNN_TC; i += 128)
            tile[i] = g_pp[b*NN + tb + i];
        __syncthreads();
#pragma unroll 4
        for (int cc = 0; cc < KNN_TC; cc++) {
            float4 c4 = tile[cc];
            // ordering-equivalent distance: |p_j|^2 - 2 <q, p_j>
            float d = fmaf(qx, c4.x, fmaf(qy, c4.y, fmaf(qz, c4.z, c4.w)));
            if (d < thr) {
                int p = 12;
#pragma unroll 1
                while (p > 0 && d < bd[p-1]) { bd[p] = bd[p-1]; bi[p] = bi[p-1]; --p; }
                bd[p] = d; bi[p] = tb + cc;
                thr = bd[12];
            }
        }
    }
#pragma unroll
    for (int r = 0; r < 12; r++)
        g_idx[(b*NN + n)*KLn + r] = bi[r+1];   // drop self (min)
}

// ---------------- P/Q GEMM: 64 points x 64 out x 64 in per tile ----------------
__global__ __launch_bounds__(128) void k_pq()
{
    __shared__ __align__(16) float Ws[4096];
    __shared__ __align__(16) float Us[4096];
    int w = blockIdx.y;                      // weight set 0..3
    int t = threadIdx.x;
    for (int i = t; i < 4096; i += 128) Ws[i] = g_Wf[w][i];

    int base = blockIdx.x * 64;              // point tile
    {   // stage X tile k-major with xor swizzle
        int e = t >> 1, h = t & 1;
        const float4* src = (const float4*)&g_xt[(base + e)*64 + h*32];
        int gg = e >> 2, eo = e & 3;
#pragma unroll
        for (int c4 = 0; c4 < 8; c4++) {
            float4 v = src[c4];
            int c = h*32 + c4*4;
            Us[(c+0)*64 + ((gg ^ ((c+0)&15))<<2) + eo] = v.x;
            Us[(c+1)*64 + ((gg ^ ((c+1)&15))<<2) + eo] = v.y;
            Us[(c+2)*64 + ((gg ^ ((c+2)&15))<<2) + eo] = v.z;
            Us[(c+3)*64 + ((gg ^ ((c+3)&15))<<2) + eo] = v.w;
        }
    }
    __syncthreads();

    int tx = t & 15, ty = t >> 4;
    float acc[8][4];
#pragma unroll
    for (int i = 0; i < 8; i++)
#pragma unroll
        for (int j = 0; j < 4; j++) acc[i][j] = 0.f;

#pragma unroll 16
    for (int k = 0; k < 64; k++) {
        float4 a0 = *(const float4*)&Ws[k*64 + ty*8];
        float4 a1 = *(const float4*)&Ws[k*64 + ty*8 + 4];
        float4 bf = *(const float4*)&Us[k*64 + ((tx ^ (k&15))<<2)];
        float a[8] = {a0.x,a0.y,a0.z,a0.w,a1.x,a1.y,a1.z,a1.w};
        float bb[4] = {bf.x,bf.y,bf.z,bf.w};
#pragma unroll
        for (int oi = 0; oi < 8; oi++)
#pragma unroll
            for (int mi = 0; mi < 4; mi++)
                acc[oi][mi] = fmaf(a[oi], bb[mi], acc[oi][mi]);
    }

    float* out = g_PQ[w];
#pragma unroll
    for (int mi = 0; mi < 4; mi++) {
        int pt = base + tx*4 + mi;
        *(float4*)&out[pt*64 + ty*8]     = make_float4(acc[0][mi],acc[1][mi],acc[2][mi],acc[3][mi]);
        *(float4*)&out[pt*64 + ty*8 + 4] = make_float4(acc[4][mi],acc[5][mi],acc[6][mi],acc[7][mi]);
    }
}

// ---------------- stats of h1 = P[i]+Q[j] over all edges ----------------
template<int K>
__global__ __launch_bounds__(256) void k_stats1()
{
    const float* __restrict__ P = g_PQ[(K==6)?0:2];
    const float* __restrict__ Q = g_PQ[(K==6)?1:3];
    const int M = NPTS*K;
    int warp = threadIdx.x >> 5, lane = threadIdx.x & 31;
    int gw = blockIdx.x*8 + warp, nw = G_STAT*8;
    float s0=0, ss0=0, s1=0, ss1=0;
    for (int m = gw; m < M; m += nw) {
        int kk = m % K, bn = m / K;
        int j  = g_idx[bn*KLn + kk];
        int b  = bn >> 13;
        const float* Pp = &P[bn*64];
        const float* Qp = &Q[(b*NN + j)*64];
        float v0 = Pp[lane]      + Qp[lane];
        float v1 = Pp[lane + 32] + Qp[lane + 32];
        s0 += v0; ss0 = fmaf(v0, v0, ss0);
        s1 += v1; ss1 = fmaf(v1, v1, ss1);
    }
    __shared__ float stg[8][128];
    stg[warp][lane]      = s0;  stg[warp][64+lane] = ss0;
    stg[warp][32+lane]   = s1;  stg[warp][96+lane] = ss1;
    __syncthreads();
    int t = threadIdx.x;
    if (t < 128) {
        float a = 0;
#pragma unroll
        for (int w2 = 0; w2 < 8; w2++) a += stg[w2][t];
        g_part[blockIdx.x*128 + t] = a;
    }
}

// ---------------- finalize BN params (deterministic serial reduce) ----------------
__global__ void k_reduce(int G, float invM, const float* __restrict__ gamma,
                         const float* __restrict__ beta, int which)
{
    int c = threadIdx.x;
    if (c < 64) {
        float S = 0.f, SS = 0.f;
        for (int g = 0; g < G; g++) { S += g_part[g*128 + c]; SS += g_part[g*128 + 64 + c]; }
        float mean = S * invM;
        float var  = SS * invM - mean*mean;
        float sc   = gamma[c] * rsqrtf(var + EPSbn);
        float sh   = beta[c] - mean*sc;
        float* dst = which ? g_bnB : g_bnA;
        dst[c] = sc; dst[64+c] = sh;
    }
}

// ---------------- conv2: per-edge  h2 = W2 * relu(bn1(P[i]+Q[j]))  + stats2 ----------------
template<int K>
__global__ __launch_bounds__(128) void k_conv2()
{
    const float* __restrict__ P   = g_PQ[(K==6)?0:2];
    const float* __restrict__ Q   = g_PQ[(K==6)?1:3];
    const float* __restrict__ W2t = g_W2t[(K==6)?0:1];
    const int nTiles = (NPTS*K)/64;

    __shared__ __align__(16) float Ws[4096];
    __shared__ __align__(16) float Us[4096];
    __shared__ float bnsc[64], bnsh[64];
    __shared__ float blockS[64], blockSS[64];
    int t = threadIdx.x;
    for (int i = t; i < 4096; i += 128) Ws[i] = W2t[i];
    if (t < 64) { bnsc[t] = g_bnA[t]; bnsh[t] = g_bnA[64+t]; }
    __syncthreads();

    int tx = t & 15, ty = t >> 4;
    float accS[8], accSS[8];
#pragma unroll
    for (int i = 0; i < 8; i++) { accS[i] = 0.f; accSS[i] = 0.f; }

    for (int tile = blockIdx.x; tile < nTiles; tile += G_CONV) {
        int mbase = tile * 64;
        __syncthreads();                       // Us reuse guard
        {   // gather + BN1 + ReLU -> Us (k-major, swizzled)
            int e = t >> 1, h = t & 1;
            int m = mbase + e;
            int kk = m % K, bn = m / K;
            int j  = g_idx[bn*KLn + kk];
            int b  = bn >> 13;
            const float4* Pp = (const float4*)&P[bn*64 + h*32];
            const float4* Qp = (const float4*)&Q[(b*NN + j)*64 + h*32];
            int gg = e >> 2, eo = e & 3;
#pragma unroll
            for (int c4 = 0; c4 < 8; c4++) {
                float4 pv = Pp[c4], qv = Qp[c4];
                int c = h*32 + c4*4;
                float u0 = fmaxf(0.f, fmaf(pv.x+qv.x, bnsc[c+0], bnsh[c+0]));
                float u1 = fmaxf(0.f, fmaf(pv.y+qv.y, bnsc[c+1], bnsh[c+1]));
                float u2 = fmaxf(0.f, fmaf(pv.z+qv.z, bnsc[c+2], bnsh[c+2]));
                float u3 = fmaxf(0.f, fmaf(pv.w+qv.w, bnsc[c+3], bnsh[c+3]));
                Us[(c+0)*64 + ((gg ^ ((c+0)&15))<<2) + eo] = u0;
                Us[(c+1)*64 + ((gg ^ ((c+1)&15))<<2) + eo] = u1;
                Us[(c+2)*64 + ((gg ^ ((c+2)&15))<<2) + eo] = u2;
                Us[(c+3)*64 + ((gg ^ ((c+3)&15))<<2) + eo] = u3;
            }
        }
        __syncthreads();

        float acc[8][4];
#pragma unroll
        for (int i = 0; i < 8; i++)
#pragma unroll
            for (int j2 = 0; j2 < 4; j2++) acc[i][j2] = 0.f;

#pragma unroll 16
        for (int k = 0; k < 64; k++) {
            float4 a0 = *(const float4*)&Ws[k*64 + ty*8];
            float4 a1 = *(const float4*)&Ws[k*64 + ty*8 + 4];
            float4 bf = *(const float4*)&Us[k*64 + ((tx ^ (k&15))<<2)];
            float a[8] = {a0.x,a0.y,a0.z,a0.w,a1.x,a1.y,a1.z,a1.w};
            float bb[4] = {bf.x,bf.y,bf.z,bf.w};
#pragma unroll
            for (int oi = 0; oi < 8; oi++)
#pragma unroll
                for (int mi = 0; mi < 4; mi++)
                    acc[oi][mi] = fmaf(a[oi], bb[mi], acc[oi][mi]);
        }

#pragma unroll
        for (int mi = 0; mi < 4; mi++) {
            int m = mbase + tx*4 + mi;
            *(float4*)&g_h2[m*64 + ty*8]     = make_float4(acc[0][mi],acc[1][mi],acc[2][mi],acc[3][mi]);
            *(float4*)&g_h2[m*64 + ty*8 + 4] = make_float4(acc[4][mi],acc[5][mi],acc[6][mi],acc[7][mi]);
        }
#pragma unroll
        for (int oi = 0; oi < 8; oi++) {
            float s = acc[oi][0] + acc[oi][1] + acc[oi][2] + acc[oi][3];
            float q = acc[oi][0]*acc[oi][0] + acc[oi][1]*acc[oi][1]
                    + acc[oi][2]*acc[oi][2] + acc[oi][3]*acc[oi][3];
            accS[oi]  += s;
            accSS[oi] += q;
        }
    }

    // reduce over the 16 tx threads sharing each channel group (within half-warp)
#pragma unroll
    for (int off = 1; off < 16; off <<= 1)
#pragma unroll
        for (int oi = 0; oi < 8; oi++) {
            accS[oi]  += __shfl_xor_sync(0xffffffffu, accS[oi],  off);
            accSS[oi] += __shfl_xor_sync(0xffffffffu, accSS[oi], off);
        }
    if (tx == 0)
#pragma unroll
        for (int oi = 0; oi < 8; oi++) { blockS[ty*8+oi] = accS[oi]; blockSS[ty*8+oi] = accSS[oi]; }
    __syncthreads();
    if (t < 128)
        g_part[blockIdx.x*128 + t] = (t < 64) ? blockS[t] : blockSS[t-64];
}

// ---------------- BN2 + ReLU + max over k -> output ----------------
template<int K>
__global__ __launch_bounds__(256) void k_out(float* __restrict__ out)
{
    const int chOff = (K==6) ? 0 : 64;
    __shared__ float res[64][33];
    int t = threadIdx.x;
    int warp = t >> 5, lane = t & 31;
    int bn0 = blockIdx.x * 32;
    int b = bn0 >> 13, n0 = bn0 & (NN-1);
    float sc0 = g_bnB[lane],      sh0 = g_bnB[64+lane];
    float sc1 = g_bnB[lane + 32], sh1 = g_bnB[96+lane];
    for (int i = 0; i < 4; i++) {
        int nl = warp*4 + i;
        int m0 = (bn0 + nl) * K;
        float v0m = -3.4e38f, v1m = -3.4e38f;
#pragma unroll
        for (int kk = 0; kk < K; kk++) {
            float v0 = g_h2[(m0+kk)*64 + lane];
            float v1 = g_h2[(m0+kk)*64 + lane + 32];
            v0m = fmaxf(v0m, fmaf(v0, sc0, sh0));
            v1m = fmaxf(v1m, fmaf(v1, sc1, sh1));
        }
        res[lane][nl]      = fmaxf(v0m, 0.f);   // relu(max) == max(relu)
        res[lane + 32][nl] = fmaxf(v1m, 0.f);
    }
    __syncthreads();
#pragma unroll
    for (int i = 0; i < 8; i++) {
        int id = t + i*256;
        int r = id >> 5, col = id & 31;
        out[((size_t)b*128 + chOff + r)*NN + n0 + col] = res[r][col];
    }
}

// ---------------- launch ----------------
extern "C" void kernel_launch(void* const* d_in, const int* in_sizes, int n_in,
                              void* d_out, int out_size)
{
    const float* x    = (const float*)d_in[0];
    const float* pos  = (const float*)d_in[1];
    const float* Ws1  = (const float*)d_in[2];
    const float* gs1  = (const float*)d_in[4];
    const float* ts1  = (const float*)d_in[5];
    const float* Ws2  = (const float*)d_in[6];
    const float* gs2  = (const float*)d_in[8];
    const float* ts2  = (const float*)d_in[9];
    const float* Wl1  = (const float*)d_in[10];
    const float* gl1  = (const float*)d_in[12];
    const float* tl1  = (const float*)d_in[13];
    const float* Wl2  = (const float*)d_in[14];
    const float* gl2  = (const float*)d_in[16];
    const float* tl2  = (const float*)d_in[17];
    float* out = (float*)d_out;

    k_prep<<<16, 256>>>(Ws1, Wl1, Ws2, Wl2);
    k_pack<<<(NPTS*CCH)/256, 256>>>(x, pos);
    k_knn<<<dim3(NN/128, BB), 128>>>();
    k_pq<<<dim3(NPTS/64, 4), 128>>>();

    // short stream (k=6), channels 0..63
    k_stats1<6><<<G_STAT, 256>>>();
    k_reduce<<<1, 64>>>(G_STAT, 1.f/(NPTS*6),  gs1, ts1, 0);
    k_conv2<6><<<G_CONV, 128>>>();
    k_reduce<<<1, 64>>>(G_CONV, 1.f/(NPTS*6),  gs2, ts2, 1);
    k_out<6><<<NPTS/32, 256>>>(out);

    // long stream (k=12), channels 64..127
    k_stats1<12><<<G_STAT, 256>>>();
    k_reduce<<<1, 64>>>(G_STAT, 1.f/(NPTS*12), gl1, tl1, 0);
    k_conv2<12><<<G_CONV, 128>>>();
    k_reduce<<<1, 64>>>(G_CONV, 1.f/(NPTS*12), gl2, tl2, 1);
    k_out<12><<<NPTS/32, 256>>>(out);
}

// round 3
// speedup vs baseline: 3.3413x; 3.3413x over previous
#include <cuda_runtime.h>

#define BB   4
#define NN   8192
#define CCH  64
#define NPTS (BB*NN)          // 32768
#define KLn  12
#define EPSbn 1e-5f
#define G_STAT 1024
#define G_CONV 1184
#define SEG   8
#define SEGC  (NN/SEG)        // 1024 candidates per segment

// ---------------- scratch (static device arrays; no allocation) ----------------
__device__ __align__(16) float  g_xt[NPTS*CCH];            // x transposed (B,N,C)   8MB
__device__ __align__(16) float4 g_pp[NPTS];                // packed points (x,y,z,|p|^2)
__device__             int    g_idx[NPTS*KLn];             // 12 NN per point (sorted)
__device__             float  g_kd[SEG*13*NPTS];           // partial knn dists 13.6MB
__device__             int    g_ki[SEG*13*NPTS];           // partial knn idx   13.6MB
__device__ __align__(16) float g_PQ[4][NPTS*CCH];          // P_s,Q_s,P_l,Q_l        32MB
__device__ __align__(16) float g_h2[NPTS*KLn*CCH];         // conv2 out scratch     100MB
__device__             float  g_part[2048*128];            // block partial stats
__device__             float  g_bnA[128];                  // layer1 scale/shift
__device__             float  g_bnB[128];                  // layer2 scale/shift
__device__ __align__(16) float g_Wf[4][4096];              // folded conv1 W, [k][o]
__device__ __align__(16) float g_W2t[2][4096];             // conv2 W transposed [k][o]

// ---------------- weight prep: fold conv1, transpose everything ----------------
__global__ void k_prep(const float* __restrict__ Ws1, const float* __restrict__ Wl1,
                       const float* __restrict__ Ws2, const float* __restrict__ Wl2)
{
    int t = blockIdx.x*blockDim.x + threadIdx.x;
    if (t < 4096) {
        int o = t >> 6, c = t & 63;
        float a0 = Ws1[o*128 + c],  a1 = Ws1[o*128 + 64 + c];
        g_Wf[0][c*64+o] = a0 - a1;          // Wa_s
        g_Wf[1][c*64+o] = a1;               // Wb_s
        float b0 = Wl1[o*128 + c],  b1 = Wl1[o*128 + 64 + c];
        g_Wf[2][c*64+o] = b0 - b1;          // Wa_l
        g_Wf[3][c*64+o] = b1;               // Wb_l
        g_W2t[0][c*64+o] = Ws2[o*64+c];
        g_W2t[1][c*64+o] = Wl2[o*64+c];
    }
}

// ---------------- pack: transpose x, build float4 points ----------------
__global__ void k_pack(const float* __restrict__ x, const float* __restrict__ pos)
{
    int t = blockIdx.x*blockDim.x + threadIdx.x;
    if (t < NPTS*CCH) {
        int c = t & 63, bn = t >> 6;
        int n = bn & (NN-1), b = bn >> 13;
        g_xt[t] = x[(b*CCH + c)*NN + n];
    }
    if (t < NPTS) {
        int n = t & (NN-1), b = t >> 13;
        float px = pos[(b*3+0)*NN + n];
        float py = pos[(b*3+1)*NN + n];
        float pz = pos[(b*3+2)*NN + n];
        g_pp[t] = make_float4(px, py, pz, px*px + py*py + pz*pz);
    }
}

// ---------------- KNN pass 1: per-segment register-resident top-13 ----------------
// Sorted top-13 kept entirely in registers: replace-last + statically unrolled
// single bubble pass (list was sorted, only slot 12 is new).
__global__ __launch_bounds__(128) void k_knn1()
{
    __shared__ __align__(16) float4 tile[SEGC];   // 16KB: whole segment
    int b   = blockIdx.z;
    int seg = blockIdx.y;
    int n   = blockIdx.x * 128 + threadIdx.x;
    int q   = b*NN + n;
    float4 qp = g_pp[q];
    float qx = -2.f*qp.x, qy = -2.f*qp.y, qz = -2.f*qp.z;
    int cbase = seg * SEGC;

    for (int i = threadIdx.x; i < SEGC; i += 128)
        tile[i] = g_pp[b*NN + cbase + i];
    __syncthreads();

    float bd[13]; int bi[13];
#pragma unroll
    for (int i = 0; i < 13; i++) { bd[i] = 3.4e38f; bi[i] = 0; }

#pragma unroll 4
    for (int cc = 0; cc < SEGC; cc++) {
        float4 c4 = tile[cc];
        // ordering-equivalent distance: |p_j|^2 - 2 <q, p_j>
        float d = fmaf(qx, c4.x, fmaf(qy, c4.y, fmaf(qz, c4.z, c4.w)));
        if (d < bd[12]) {
            bd[12] = d; bi[12] = cbase + cc;
#pragma unroll
            for (int j = 12; j > 0; j--) {
                if (bd[j] < bd[j-1]) {
                    float td = bd[j]; bd[j] = bd[j-1]; bd[j-1] = td;
                    int   ti = bi[j]; bi[j] = bi[j-1]; bi[j-1] = ti;
                }
            }
        }
    }

    // layout [(seg*13+r)][q] -> coalesced across lanes on both write and read
#pragma unroll
    for (int r = 0; r < 13; r++) {
        g_kd[(seg*13 + r)*NPTS + q] = bd[r];
        g_ki[(seg*13 + r)*NPTS + q] = bi[r];
    }
}

// ---------------- KNN pass 2: merge 8 sorted partials, drop self ----------------
__global__ __launch_bounds__(256) void k_knn2()
{
    int q = blockIdx.x*256 + threadIdx.x;
    float bd[13]; int bi[13];
#pragma unroll
    for (int i = 0; i < 13; i++) { bd[i] = 3.4e38f; bi[i] = 0; }

    for (int s = 0; s < SEG; s++) {
#pragma unroll
        for (int r = 0; r < 13; r++) {
            float d = g_kd[(s*13 + r)*NPTS + q];
            if (d >= bd[12]) break;            // partial list is sorted ascending
            int idx = g_ki[(s*13 + r)*NPTS + q];
            bd[12] = d; bi[12] = idx;
#pragma unroll
            for (int j = 12; j > 0; j--) {
                if (bd[j] < bd[j-1]) {
                    float td = bd[j]; bd[j] = bd[j-1]; bd[j-1] = td;
                    int   ti = bi[j]; bi[j] = bi[j-1]; bi[j-1] = ti;
                }
            }
        }
    }
    // bd[0] is self (strict global minimum) -> emit entries 1..12
#pragma unroll
    for (int r = 0; r < 12; r++)
        g_idx[q*KLn + r] = bi[r+1];
}

// ---------------- P/Q GEMM: 64 points x 64 out x 64 in per tile ----------------
__global__ __launch_bounds__(128) void k_pq()
{
    __shared__ __align__(16) float Ws[4096];
    __shared__ __align__(16) float Us[4096];
    int w = blockIdx.y;                      // weight set 0..3
    int t = threadIdx.x;
    for (int i = t; i < 4096; i += 128) Ws[i] = g_Wf[w][i];

    int base = blockIdx.x * 64;              // point tile
    {   // stage X tile k-major with xor swizzle
        int e = t >> 1, h = t & 1;
        const float4* src = (const float4*)&g_xt[(base + e)*64 + h*32];
        int gg = e >> 2, eo = e & 3;
#pragma unroll
        for (int c4 = 0; c4 < 8; c4++) {
            float4 v = src[c4];
            int c = h*32 + c4*4;
            Us[(c+0)*64 + ((gg ^ ((c+0)&15))<<2) + eo] = v.x;
            Us[(c+1)*64 + ((gg ^ ((c+1)&15))<<2) + eo] = v.y;
            Us[(c+2)*64 + ((gg ^ ((c+2)&15))<<2) + eo] = v.z;
            Us[(c+3)*64 + ((gg ^ ((c+3)&15))<<2) + eo] = v.w;
        }
    }
    __syncthreads();

    int tx = t & 15, ty = t >> 4;
    float acc[8][4];
#pragma unroll
    for (int i = 0; i < 8; i++)
#pragma unroll
        for (int j = 0; j < 4; j++) acc[i][j] = 0.f;

#pragma unroll 16
    for (int k = 0; k < 64; k++) {
        float4 a0 = *(const float4*)&Ws[k*64 + ty*8];
        float4 a1 = *(const float4*)&Ws[k*64 + ty*8 + 4];
        float4 bf = *(const float4*)&Us[k*64 + ((tx ^ (k&15))<<2)];
        float a[8] = {a0.x,a0.y,a0.z,a0.w,a1.x,a1.y,a1.z,a1.w};
        float bb[4] = {bf.x,bf.y,bf.z,bf.w};
#pragma unroll
        for (int oi = 0; oi < 8; oi++)
#pragma unroll
            for (int mi = 0; mi < 4; mi++)
                acc[oi][mi] = fmaf(a[oi], bb[mi], acc[oi][mi]);
    }

    float* out = g_PQ[w];
#pragma unroll
    for (int mi = 0; mi < 4; mi++) {
        int pt = base + tx*4 + mi;
        *(float4*)&out[pt*64 + ty*8]     = make_float4(acc[0][mi],acc[1][mi],acc[2][mi],acc[3][mi]);
        *(float4*)&out[pt*64 + ty*8 + 4] = make_float4(acc[4][mi],acc[5][mi],acc[6][mi],acc[7][mi]);
    }
}

// ---------------- stats of h1 = P[i]+Q[j] over all edges ----------------
template<int K>
__global__ __launch_bounds__(256) void k_stats1()
{
    const float* __restrict__ P = g_PQ[(K==6)?0:2];
    const float* __restrict__ Q = g_PQ[(K==6)?1:3];
    const int M = NPTS*K;
    int warp = threadIdx.x >> 5, lane = threadIdx.x & 31;
    int gw = blockIdx.x*8 + warp, nw = G_STAT*8;
    float s0=0, ss0=0, s1=0, ss1=0;
    for (int m = gw; m < M; m += nw) {
        int kk = m % K, bn = m / K;
        int j  = g_idx[bn*KLn + kk];
        int b  = bn >> 13;
        const float* Pp = &P[bn*64];
        const float* Qp = &Q[(b*NN + j)*64];
        float v0 = Pp[lane]      + Qp[lane];
        float v1 = Pp[lane + 32] + Qp[lane + 32];
        s0 += v0; ss0 = fmaf(v0, v0, ss0);
        s1 += v1; ss1 = fmaf(v1, v1, ss1);
    }
    __shared__ float stg[8][128];
    stg[warp][lane]      = s0;  stg[warp][64+lane] = ss0;
    stg[warp][32+lane]   = s1;  stg[warp][96+lane] = ss1;
    __syncthreads();
    int t = threadIdx.x;
    if (t < 128) {
        float a = 0;
#pragma unroll
        for (int w2 = 0; w2 < 8; w2++) a += stg[w2][t];
        g_part[blockIdx.x*128 + t] = a;
    }
}

// ---------------- finalize BN params (deterministic serial reduce) ----------------
__global__ void k_reduce(int G, float invM, const float* __restrict__ gamma,
                         const float* __restrict__ beta, int which)
{
    int c = threadIdx.x;
    if (c < 64) {
        float S = 0.f, SS = 0.f;
        for (int g = 0; g < G; g++) { S += g_part[g*128 + c]; SS += g_part[g*128 + 64 + c]; }
        float mean = S * invM;
        float var  = SS * invM - mean*mean;
        float sc   = gamma[c] * rsqrtf(var + EPSbn);
        float sh   = beta[c] - mean*sc;
        float* dst = which ? g_bnB : g_bnA;
        dst[c] = sc; dst[64+c] = sh;
    }
}

// ---------------- conv2: per-edge  h2 = W2 * relu(bn1(P[i]+Q[j]))  + stats2 ----------------
template<int K>
__global__ __launch_bounds__(128) void k_conv2()
{
    const float* __restrict__ P   = g_PQ[(K==6)?0:2];
    const float* __restrict__ Q   = g_PQ[(K==6)?1:3];
    const float* __restrict__ W2t = g_W2t[(K==6)?0:1];
    const int nTiles = (NPTS*K)/64;

    __shared__ __align__(16) float Ws[4096];
    __shared__ __align__(16) float Us[4096];
    __shared__ float bnsc[64], bnsh[64];
    __shared__ float blockS[64], blockSS[64];
    int t = threadIdx.x;
    for (int i = t; i < 4096; i += 128) Ws[i] = W2t[i];
    if (t < 64) { bnsc[t] = g_bnA[t]; bnsh[t] = g_bnA[64+t]; }
    __syncthreads();

    int tx = t & 15, ty = t >> 4;
    float accS[8], accSS[8];
#pragma unroll
    for (int i = 0; i < 8; i++) { accS[i] = 0.f; accSS[i] = 0.f; }

    for (int tile = blockIdx.x; tile < nTiles; tile += G_CONV) {
        int mbase = tile * 64;
        __syncthreads();                       // Us reuse guard
        {   // gather + BN1 + ReLU -> Us (k-major, swizzled)
            int e = t >> 1, h = t & 1;
            int m = mbase + e;
            int kk = m % K, bn = m / K;
            int j  = g_idx[bn*KLn + kk];
            int b  = bn >> 13;
            const float4* Pp = (const float4*)&P[bn*64 + h*32];
            const float4* Qp = (const float4*)&Q[(b*NN + j)*64 + h*32];
            int gg = e >> 2, eo = e & 3;
#pragma unroll
            for (int c4 = 0; c4 < 8; c4++) {
                float4 pv = Pp[c4], qv = Qp[c4];
                int c = h*32 + c4*4;
                float u0 = fmaxf(0.f, fmaf(pv.x+qv.x, bnsc[c+0], bnsh[c+0]));
                float u1 = fmaxf(0.f, fmaf(pv.y+qv.y, bnsc[c+1], bnsh[c+1]));
                float u2 = fmaxf(0.f, fmaf(pv.z+qv.z, bnsc[c+2], bnsh[c+2]));
                float u3 = fmaxf(0.f, fmaf(pv.w+qv.w, bnsc[c+3], bnsh[c+3]));
                Us[(c+0)*64 + ((gg ^ ((c+0)&15))<<2) + eo] = u0;
                Us[(c+1)*64 + ((gg ^ ((c+1)&15))<<2) + eo] = u1;
                Us[(c+2)*64 + ((gg ^ ((c+2)&15))<<2) + eo] = u2;
                Us[(c+3)*64 + ((gg ^ ((c+3)&15))<<2) + eo] = u3;
            }
        }
        __syncthreads();

        float acc[8][4];
#pragma unroll
        for (int i = 0; i < 8; i++)
#pragma unroll
            for (int j2 = 0; j2 < 4; j2++) acc[i][j2] = 0.f;

#pragma unroll 16
        for (int k = 0; k < 64; k++) {
            float4 a0 = *(const float4*)&Ws[k*64 + ty*8];
            float4 a1 = *(const float4*)&Ws[k*64 + ty*8 + 4];
            float4 bf = *(const float4*)&Us[k*64 + ((tx ^ (k&15))<<2)];
            float a[8] = {a0.x,a0.y,a0.z,a0.w,a1.x,a1.y,a1.z,a1.w};
            float bb[4] = {bf.x,bf.y,bf.z,bf.w};
#pragma unroll
            for (int oi = 0; oi < 8; oi++)
#pragma unroll
                for (int mi = 0; mi < 4; mi++)
                    acc[oi][mi] = fmaf(a[oi], bb[mi], acc[oi][mi]);
        }

#pragma unroll
        for (int mi = 0; mi < 4; mi++) {
            int m = mbase + tx*4 + mi;
            *(float4*)&g_h2[m*64 + ty*8]     = make_float4(acc[0][mi],acc[1][mi],acc[2][mi],acc[3][mi]);
            *(float4*)&g_h2[m*64 + ty*8 + 4] = make_float4(acc[4][mi],acc[5][mi],acc[6][mi],acc[7][mi]);
        }
#pragma unroll
        for (int oi = 0; oi < 8; oi++) {
            float s = acc[oi][0] + acc[oi][1] + acc[oi][2] + acc[oi][3];
            float q = acc[oi][0]*acc[oi][0] + acc[oi][1]*acc[oi][1]
                    + acc[oi][2]*acc[oi][2] + acc[oi][3]*acc[oi][3];
            accS[oi]  += s;
            accSS[oi] += q;
        }
    }

    // reduce over the 16 tx threads sharing each channel group (within half-warp)
#pragma unroll
    for (int off = 1; off < 16; off <<= 1)
#pragma unroll
        for (int oi = 0; oi < 8; oi++) {
            accS[oi]  += __shfl_xor_sync(0xffffffffu, accS[oi],  off);
            accSS[oi] += __shfl_xor_sync(0xffffffffu, accSS[oi], off);
        }
    if (tx == 0)
#pragma unroll
        for (int oi = 0; oi < 8; oi++) { blockS[ty*8+oi] = accS[oi]; blockSS[ty*8+oi] = accSS[oi]; }
    __syncthreads();
    if (t < 128)
        g_part[blockIdx.x*128 + t] = (t < 64) ? blockS[t] : blockSS[t-64];
}

// ---------------- BN2 + ReLU + max over k -> output ----------------
template<int K>
__global__ __launch_bounds__(256) void k_out(float* __restrict__ out)
{
    const int chOff = (K==6) ? 0 : 64;
    __shared__ float res[64][33];
    int t = threadIdx.x;
    int warp = t >> 5, lane = t & 31;
    int bn0 = blockIdx.x * 32;
    int b = bn0 >> 13, n0 = bn0 & (NN-1);
    float sc0 = g_bnB[lane],      sh0 = g_bnB[64+lane];
    float sc1 = g_bnB[lane + 32], sh1 = g_bnB[96+lane];
    for (int i = 0; i < 4; i++) {
        int nl = warp*4 + i;
        int m0 = (bn0 + nl) * K;
        float v0m = -3.4e38f, v1m = -3.4e38f;
#pragma unroll
        for (int kk = 0; kk < K; kk++) {
            float v0 = g_h2[(m0+kk)*64 + lane];
            float v1 = g_h2[(m0+kk)*64 + lane + 32];
            v0m = fmaxf(v0m, fmaf(v0, sc0, sh0));
            v1m = fmaxf(v1m, fmaf(v1, sc1, sh1));
        }
        res[lane][nl]      = fmaxf(v0m, 0.f);   // relu(max) == max(relu)
        res[lane + 32][nl] = fmaxf(v1m, 0.f);
    }
    __syncthreads();
#pragma unroll
    for (int i = 0; i < 8; i++) {
        int id = t + i*256;
        int r = id >> 5, col = id & 31;
        out[((size_t)b*128 + chOff + r)*NN + n0 + col] = res[r][col];
    }
}

// ---------------- launch ----------------
extern "C" void kernel_launch(void* const* d_in, const int* in_sizes, int n_in,
                              void* d_out, int out_size)
{
    const float* x    = (const float*)d_in[0];
    const float* pos  = (const float*)d_in[1];
    const float* Ws1  = (const float*)d_in[2];
    const float* gs1  = (const float*)d_in[4];
    const float* ts1  = (const float*)d_in[5];
    const float* Ws2  = (const float*)d_in[6];
    const float* gs2  = (const float*)d_in[8];
    const float* ts2  = (const float*)d_in[9];
    const float* Wl1  = (const float*)d_in[10];
    const float* gl1  = (const float*)d_in[12];
    const float* tl1  = (const float*)d_in[13];
    const float* Wl2  = (const float*)d_in[14];
    const float* gl2  = (const float*)d_in[16];
    const float* tl2  = (const float*)d_in[17];
    float* out = (float*)d_out;

    k_prep<<<16, 256>>>(Ws1, Wl1, Ws2, Wl2);
    k_pack<<<(NPTS*CCH)/256, 256>>>(x, pos);
    k_knn1<<<dim3(NN/128, SEG, BB), 128>>>();
    k_knn2<<<NPTS/256, 256>>>();
    k_pq<<<dim3(NPTS/64, 4), 128>>>();

    // short stream (k=6), channels 0..63
    k_stats1<6><<<G_STAT, 256>>>();
    k_reduce<<<1, 64>>>(G_STAT, 1.f/(NPTS*6),  gs1, ts1, 0);
    k_conv2<6><<<G_CONV, 128>>>();
    k_reduce<<<1, 64>>>(G_CONV, 1.f/(NPTS*6),  gs2, ts2, 1);
    k_out<6><<<NPTS/32, 256>>>(out);

    // long stream (k=12), channels 64..127
    k_stats1<12><<<G_STAT, 256>>>();
    k_reduce<<<1, 64>>>(G_STAT, 1.f/(NPTS*12), gl1, tl1, 0);
    k_conv2<12><<<G_CONV, 128>>>();
    k_reduce<<<1, 64>>>(G_CONV, 1.f/(NPTS*12), gl2, tl2, 1);
    k_out<12><<<NPTS/32, 256>>>(out);
}

// round 4
// speedup vs baseline: 4.4194x; 1.3227x over previous
#include <cuda_runtime.h>

#define BB   4
#define NN   8192
#define CCH  64
#define NPTS (BB*NN)          // 32768
#define KLn  12
#define EPSbn 1e-5f
#define G_STAT 1024
#define G_CONV 1184
#define SEG   4
#define SEGC  (NN/SEG)        // 2048 candidates per segment
#define MT   96               // conv2 edge-tile (divisible by 6 and 12)

// ---------------- scratch (static device arrays; no allocation) ----------------
__device__ __align__(16) float  g_xt[NPTS*CCH];            // x transposed (B,N,C)   8MB
__device__ __align__(16) float4 g_pp[NPTS];                // packed points (x,y,z,|p|^2)
__device__             int    g_idx[NPTS*KLn];             // 12 NN per point (sorted)
__device__             float  g_kd[SEG*13*NPTS];           // partial knn dists
__device__             int    g_ki[SEG*13*NPTS];           // partial knn idx
__device__ __align__(16) float g_PQ[4][NPTS*CCH];          // P_s,Q_s,P_l,Q_l        32MB
__device__ __align__(16) float g_mx[NPTS*CCH];             // per-(pt,ch) max of h2   8MB
__device__ __align__(16) float g_mn[NPTS*CCH];             // per-(pt,ch) min of h2   8MB
__device__             float  g_part[2048*128];            // block partial stats
__device__             float  g_bnA[128];                  // layer1 scale/shift
__device__             float  g_bnB[128];                  // layer2 scale/shift
__device__ __align__(16) float g_Wf[4][4096];              // folded conv1 W, [k][o]
__device__ __align__(16) float g_W2t[2][4096];             // conv2 W transposed [k][o]

// ---------------- f32x2 helpers ----------------
__device__ __forceinline__ unsigned long long pk2(float lo, float hi) {
    unsigned long long r;
    asm("mov.b64 %0, {%1,%2};" : "=l"(r) : "f"(lo), "f"(hi));
    return r;
}
__device__ __forceinline__ unsigned long long dup2(float v) { return pk2(v, v); }
__device__ __forceinline__ void upk2(unsigned long long r, float& lo, float& hi) {
    asm("mov.b64 {%0,%1}, %2;" : "=f"(lo), "=f"(hi) : "l"(r));
}
__device__ __forceinline__ unsigned long long ffma2(unsigned long long a,
                                                    unsigned long long b,
                                                    unsigned long long c) {
    unsigned long long d;
    asm("fma.rn.f32x2 %0, %1, %2, %3;" : "=l"(d) : "l"(a), "l"(b), "l"(c));
    return d;
}

// ---------------- weight prep: fold conv1, transpose everything ----------------
__global__ void k_prep(const float* __restrict__ Ws1, const float* __restrict__ Wl1,
                       const float* __restrict__ Ws2, const float* __restrict__ Wl2)
{
    int t = blockIdx.x*blockDim.x + threadIdx.x;
    if (t < 4096) {
        int o = t >> 6, c = t & 63;
        float a0 = Ws1[o*128 + c],  a1 = Ws1[o*128 + 64 + c];
        g_Wf[0][c*64+o] = a0 - a1;          // Wa_s
        g_Wf[1][c*64+o] = a1;               // Wb_s
        float b0 = Wl1[o*128 + c],  b1 = Wl1[o*128 + 64 + c];
        g_Wf[2][c*64+o] = b0 - b1;          // Wa_l
        g_Wf[3][c*64+o] = b1;               // Wb_l
        g_W2t[0][c*64+o] = Ws2[o*64+c];
        g_W2t[1][c*64+o] = Wl2[o*64+c];
    }
}

// ---------------- pack pos into float4 ----------------
__global__ void k_pos(const float* __restrict__ pos)
{
    int t = blockIdx.x*blockDim.x + threadIdx.x;
    if (t < NPTS) {
        int n = t & (NN-1), b = t >> 13;
        float px = pos[(b*3+0)*NN + n];
        float py = pos[(b*3+1)*NN + n];
        float pz = pos[(b*3+2)*NN + n];
        g_pp[t] = make_float4(px, py, pz, px*px + py*py + pz*pz);
    }
}

// ---------------- coalesced tiled transpose of x ----------------
__global__ __launch_bounds__(256) void k_pack(const float* __restrict__ x)
{
    __shared__ float tile[32][33];
    int b  = blockIdx.z;
    int c0 = blockIdx.y * 32;
    int n0 = blockIdx.x * 32;
    int tx = threadIdx.x & 31, ty = threadIdx.x >> 5;   // ty 0..7
#pragma unroll
    for (int i = 0; i < 4; i++) {
        int r = ty + 8*i;                               // channel row
        tile[r][tx] = x[((size_t)(b*CCH + c0 + r))*NN + n0 + tx];
    }
    __syncthreads();
#pragma unroll
    for (int i = 0; i < 4; i++) {
        int r = ty + 8*i;                               // n row
        g_xt[((size_t)(b*NN + n0 + r))*64 + c0 + tx] = tile[tx][r];
    }
}

// ---------------- KNN pass 1: per-segment register-resident top-13 ----------------
__global__ __launch_bounds__(128) void k_knn1()
{
    __shared__ __align__(16) float4 tile[SEGC];   // 32KB segment
    int b   = blockIdx.z;
    int seg = blockIdx.y;
    int n   = blockIdx.x * 128 + threadIdx.x;
    int q   = b*NN + n;
    float4 qp = g_pp[q];
    float qx = -2.f*qp.x, qy = -2.f*qp.y, qz = -2.f*qp.z;
    int cbase = seg * SEGC;

    for (int i = threadIdx.x; i < SEGC; i += 128)
        tile[i] = g_pp[b*NN + cbase + i];
    __syncthreads();

    float bd[13]; int bi[13];
#pragma unroll
    for (int i = 0; i < 13; i++) { bd[i] = 3.4e38f; bi[i] = 0; }

#pragma unroll 4
    for (int cc = 0; cc < SEGC; cc++) {
        float4 c4 = tile[cc];
        float d = fmaf(qx, c4.x, fmaf(qy, c4.y, fmaf(qz, c4.z, c4.w)));
        if (d < bd[12]) {
            bd[12] = d; bi[12] = cbase + cc;
#pragma unroll
            for (int j = 12; j > 0; j--) {
                if (bd[j] < bd[j-1]) {
                    float td = bd[j]; bd[j] = bd[j-1]; bd[j-1] = td;
                    int   ti = bi[j]; bi[j] = bi[j-1]; bi[j-1] = ti;
                }
            }
        }
    }
#pragma unroll
    for (int r = 0; r < 13; r++) {
        g_kd[(seg*13 + r)*NPTS + q] = bd[r];
        g_ki[(seg*13 + r)*NPTS + q] = bi[r];
    }
}

// ---------------- KNN pass 2: merge sorted partials, drop self ----------------
__global__ __launch_bounds__(128) void k_knn2()
{
    int q = blockIdx.x*128 + threadIdx.x;
    float bd[13]; int bi[13];
#pragma unroll
    for (int i = 0; i < 13; i++) { bd[i] = 3.4e38f; bi[i] = 0; }

    for (int s = 0; s < SEG; s++) {
#pragma unroll
        for (int r = 0; r < 13; r++) {
            float d = g_kd[(s*13 + r)*NPTS + q];
            if (d >= bd[12]) break;            // partial list is sorted ascending
            int idx = g_ki[(s*13 + r)*NPTS + q];
            bd[12] = d; bi[12] = idx;
#pragma unroll
            for (int j = 12; j > 0; j--) {
                if (bd[j] < bd[j-1]) {
                    float td = bd[j]; bd[j] = bd[j-1]; bd[j-1] = td;
                    int   ti = bi[j]; bi[j] = bi[j-1]; bi[j-1] = ti;
                }
            }
        }
    }
#pragma unroll
    for (int r = 0; r < 12; r++)
        g_idx[q*KLn + r] = bi[r+1];            // bd[0] is self
}

// ---------------- P/Q GEMM with f32x2 FMA ----------------
__global__ __launch_bounds__(128) void k_pq()
{
    __shared__ __align__(16) float Ws[4096];
    __shared__ __align__(16) float Us[4096];
    int w = blockIdx.y;
    int t = threadIdx.x;
    for (int i = t; i < 4096; i += 128) Ws[i] = g_Wf[w][i];

    int base = blockIdx.x * 64;
    {   // stage X tile k-major with xor swizzle
        int e = t >> 1, h = t & 1;
        const float4* src = (const float4*)&g_xt[(base + e)*64 + h*32];
        int gg = e >> 2, eo = e & 3;
#pragma unroll
        for (int c4 = 0; c4 < 8; c4++) {
            float4 v = src[c4];
            int c = h*32 + c4*4;
            Us[(c+0)*64 + ((gg ^ ((c+0)&15))<<2) + eo] = v.x;
            Us[(c+1)*64 + ((gg ^ ((c+1)&15))<<2) + eo] = v.y;
            Us[(c+2)*64 + ((gg ^ ((c+2)&15))<<2) + eo] = v.z;
            Us[(c+3)*64 + ((gg ^ ((c+3)&15))<<2) + eo] = v.w;
        }
    }
    __syncthreads();

    int tx = t & 15, ty = t >> 4;
    unsigned long long acc2[4][4];             // [oi-pair][mi]
#pragma unroll
    for (int i = 0; i < 4; i++)
#pragma unroll
        for (int j = 0; j < 4; j++) acc2[i][j] = 0ULL;

#pragma unroll 8
    for (int k = 0; k < 64; k++) {
        const unsigned long long* ap = (const unsigned long long*)&Ws[k*64 + ty*8];
        unsigned long long a2[4] = {ap[0], ap[1], ap[2], ap[3]};
        float4 bf = *(const float4*)&Us[k*64 + ((tx ^ (k&15))<<2)];
        unsigned long long b2[4] = {dup2(bf.x), dup2(bf.y), dup2(bf.z), dup2(bf.w)};
#pragma unroll
        for (int oi = 0; oi < 4; oi++)
#pragma unroll
            for (int mi = 0; mi < 4; mi++)
                acc2[oi][mi] = ffma2(a2[oi], b2[mi], acc2[oi][mi]);
    }

    float* out = g_PQ[w];
#pragma unroll
    for (int mi = 0; mi < 4; mi++) {
        float a[8];
#pragma unroll
        for (int oi = 0; oi < 4; oi++) upk2(acc2[oi][mi], a[2*oi], a[2*oi+1]);
        int pt = base + tx*4 + mi;
        *(float4*)&out[pt*64 + ty*8]     = make_float4(a[0],a[1],a[2],a[3]);
        *(float4*)&out[pt*64 + ty*8 + 4] = make_float4(a[4],a[5],a[6],a[7]);
    }
}

// ---------------- stats of h1 = P[i]+Q[j] over all edges ----------------
template<int K>
__global__ __launch_bounds__(256) void k_stats1()
{
    const float* __restrict__ P = g_PQ[(K==6)?0:2];
    const float* __restrict__ Q = g_PQ[(K==6)?1:3];
    const int M = NPTS*K;
    int warp = threadIdx.x >> 5, lane = threadIdx.x & 31;
    int gw = blockIdx.x*8 + warp, nw = G_STAT*8;
    float s0=0, ss0=0, s1=0, ss1=0;
    for (int m = gw; m < M; m += nw) {
        int kk = m % K, bn = m / K;
        int j  = g_idx[bn*KLn + kk];
        int b  = bn >> 13;
        const float* Pp = &P[bn*64];
        const float* Qp = &Q[(b*NN + j)*64];
        float v0 = Pp[lane]      + Qp[lane];
        float v1 = Pp[lane + 32] + Qp[lane + 32];
        s0 += v0; ss0 = fmaf(v0, v0, ss0);
        s1 += v1; ss1 = fmaf(v1, v1, ss1);
    }
    __shared__ float stg[8][128];
    stg[warp][lane]      = s0;  stg[warp][64+lane] = ss0;
    stg[warp][32+lane]   = s1;  stg[warp][96+lane] = ss1;
    __syncthreads();
    int t = threadIdx.x;
    if (t < 128) {
        float a = 0;
#pragma unroll
        for (int w2 = 0; w2 < 8; w2++) a += stg[w2][t];
        g_part[blockIdx.x*128 + t] = a;
    }
}

// ---------------- finalize BN params (parallel, deterministic) ----------------
__global__ __launch_bounds__(256) void k_reduce(int G, float invM,
                         const float* __restrict__ gamma,
                         const float* __restrict__ beta, int which)
{
    __shared__ float sm[8][64];
    int t = threadIdx.x;
    int c = t & 63, grp = t >> 6;              // 4 groups
    int chunk = (G + 3) >> 2;
    int g0 = grp*chunk, g1 = min(G, g0 + chunk);
    float S = 0.f, SS = 0.f;
    for (int g = g0; g < g1; g++) { S += g_part[g*128 + c]; SS += g_part[g*128 + 64 + c]; }
    sm[grp][c] = S; sm[4+grp][c] = SS;
    __syncthreads();
    if (t < 64) {
        float Sa = 0.f, SSa = 0.f;
#pragma unroll
        for (int g = 0; g < 4; g++) { Sa += sm[g][t]; SSa += sm[4+g][t]; }
        float mean = Sa * invM;
        float var  = SSa * invM - mean*mean;
        float sc   = gamma[t] * rsqrtf(var + EPSbn);
        float sh   = beta[t] - mean*sc;
        float* dst = which ? g_bnB : g_bnA;
        dst[t] = sc; dst[64+t] = sh;
    }
}

// ---------------- conv2: 96-edge tiles, f32x2 GEMM, fused min/max over k ----------------
template<int K>
__global__ __launch_bounds__(128) void k_conv2()
{
    const float* __restrict__ P   = g_PQ[(K==6)?0:2];
    const float* __restrict__ Q   = g_PQ[(K==6)?1:3];
    const float* __restrict__ W2t = g_W2t[(K==6)?0:1];
    const int nTiles = (NPTS*K)/MT;
    const int PPT = MT/K;                      // whole points per tile

    __shared__ __align__(16) float Ws[4096];
    __shared__ __align__(16) float Ub[6336];   // union: Us 64x97 / h2s 96x66
    __shared__ float bnsc[64], bnsh[64];
    __shared__ float blockS[64], blockSS[64];
    int t = threadIdx.x;
    for (int i = t; i < 4096; i += 128) Ws[i] = W2t[i];
    if (t < 64) { bnsc[t] = g_bnA[t]; bnsh[t] = g_bnA[64+t]; }
    __syncthreads();

    int tx = t & 15, ty = t >> 4;
    float accS[8], accSS[8];
#pragma unroll
    for (int i = 0; i < 8; i++) { accS[i] = 0.f; accSS[i] = 0.f; }

    for (int tile = blockIdx.x; tile < nTiles; tile += G_CONV) {
        int mbase = tile * MT;
        __syncthreads();                       // Ub reuse guard
        // gather + BN1 + ReLU -> Us (k-major, row stride 97)
        for (int u = t; u < 2*MT; u += 128) {
            int e = u >> 1, h = u & 1;
            int m = mbase + e;
            int kk = m % K, bn = m / K;
            int j  = g_idx[bn*KLn + kk];
            int b  = bn >> 13;
            const float4* Pp = (const float4*)&P[bn*64 + h*32];
            const float4* Qp = (const float4*)&Q[(b*NN + j)*64 + h*32];
#pragma unroll
            for (int c4 = 0; c4 < 8; c4++) {
                float4 pv = Pp[c4], qv = Qp[c4];
                int c = h*32 + c4*4;
                Ub[(c+0)*97 + e] = fmaxf(0.f, fmaf(pv.x+qv.x, bnsc[c+0], bnsh[c+0]));
                Ub[(c+1)*97 + e] = fmaxf(0.f, fmaf(pv.y+qv.y, bnsc[c+1], bnsh[c+1]));
                Ub[(c+2)*97 + e] = fmaxf(0.f, fmaf(pv.z+qv.z, bnsc[c+2], bnsh[c+2]));
                Ub[(c+3)*97 + e] = fmaxf(0.f, fmaf(pv.w+qv.w, bnsc[c+3], bnsh[c+3]));
            }
        }
        __syncthreads();

        // GEMM: edges e = tx + 16*mi (mi<6), channels ty*8..ty*8+7 (as 4 pairs)
        unsigned long long acc2[4][6];
#pragma unroll
        for (int i = 0; i < 4; i++)
#pragma unroll
            for (int j2 = 0; j2 < 6; j2++) acc2[i][j2] = 0ULL;

#pragma unroll 8
        for (int k = 0; k < 64; k++) {
            const unsigned long long* ap = (const unsigned long long*)&Ws[k*64 + ty*8];
            unsigned long long a2[4] = {ap[0], ap[1], ap[2], ap[3]};
            unsigned long long b2[6];
#pragma unroll
            for (int mi = 0; mi < 6; mi++)
                b2[mi] = dup2(Ub[k*97 + tx + 16*mi]);
#pragma unroll
            for (int oi = 0; oi < 4; oi++)
#pragma unroll
                for (int mi = 0; mi < 6; mi++)
                    acc2[oi][mi] = ffma2(a2[oi], b2[mi], acc2[oi][mi]);
        }
        __syncthreads();                       // Us dead; reuse Ub for h2s

        // unpack: stats accumulation + write h2 tile to shared (row stride 66)
#pragma unroll
        for (int mi = 0; mi < 6; mi++) {
            int e = tx + 16*mi;
            float v[8];
#pragma unroll
            for (int oi = 0; oi < 4; oi++) upk2(acc2[oi][mi], v[2*oi], v[2*oi+1]);
#pragma unroll
            for (int oi = 0; oi < 8; oi++) {
                accS[oi]  += v[oi];
                accSS[oi] = fmaf(v[oi], v[oi], accSS[oi]);
            }
#pragma unroll
            for (int oi = 0; oi < 4; oi++)
                *(float2*)&Ub[e*66 + ty*8 + 2*oi] = make_float2(v[2*oi], v[2*oi+1]);
        }
        __syncthreads();

        // per-(point,channel) min/max over K edges (tile holds whole points)
        for (int s = t; s < PPT*64; s += 128) {
            int p = s >> 6, ch = s & 63;
            float vmax = -3.4e38f, vmin = 3.4e38f;
#pragma unroll
            for (int kk = 0; kk < K; kk++) {
                float v = Ub[(p*K + kk)*66 + ch];
                vmax = fmaxf(vmax, v); vmin = fminf(vmin, v);
            }
            int pt = mbase/K + p;
            g_mx[pt*64 + ch] = vmax;
            g_mn[pt*64 + ch] = vmin;
        }
    }

    // cross-thread stats reduce over tx lanes
#pragma unroll
    for (int off = 1; off < 16; off <<= 1)
#pragma unroll
        for (int oi = 0; oi < 8; oi++) {
            accS[oi]  += __shfl_xor_sync(0xffffffffu, accS[oi],  off);
            accSS[oi] += __shfl_xor_sync(0xffffffffu, accSS[oi], off);
        }
    if (tx == 0)
#pragma unroll
        for (int oi = 0; oi < 8; oi++) { blockS[ty*8+oi] = accS[oi]; blockSS[ty*8+oi] = accSS[oi]; }
    __syncthreads();
    if (t < 128)
        g_part[blockIdx.x*128 + t] = (t < 64) ? blockS[t] : blockSS[t-64];
}

// ---------------- BN2 + ReLU + max -> output (from min/max buffers) ----------------
template<int K>
__global__ __launch_bounds__(256) void k_out(float* __restrict__ out)
{
    const int chOff = (K==6) ? 0 : 64;
    __shared__ float res[64][33];
    int t = threadIdx.x;
    int warp = t >> 5, lane = t & 31;
    int bn0 = blockIdx.x * 32;
    int b = bn0 >> 13, n0 = bn0 & (NN-1);
    float sc0 = g_bnB[lane],      sh0 = g_bnB[64+lane];
    float sc1 = g_bnB[lane + 32], sh1 = g_bnB[96+lane];
#pragma unroll
    for (int i = 0; i < 4; i++) {
        int nl = warp*4 + i;
        int pt = bn0 + nl;
        float h0 = (sc0 >= 0.f) ? g_mx[pt*64 + lane]      : g_mn[pt*64 + lane];
        float h1 = (sc1 >= 0.f) ? g_mx[pt*64 + lane + 32] : g_mn[pt*64 + lane + 32];
        res[lane][nl]      = fmaxf(0.f, fmaf(h0, sc0, sh0));
        res[lane + 32][nl] = fmaxf(0.f, fmaf(h1, sc1, sh1));
    }
    __syncthreads();
#pragma unroll
    for (int i = 0; i < 8; i++) {
        int id = t + i*256;
        int r = id >> 5, col = id & 31;
        out[((size_t)b*128 + chOff + r)*NN + n0 + col] = res[r][col];
    }
}

// ---------------- launch ----------------
extern "C" void kernel_launch(void* const* d_in, const int* in_sizes, int n_in,
                              void* d_out, int out_size)
{
    const float* x    = (const float*)d_in[0];
    const float* pos  = (const float*)d_in[1];
    const float* Ws1  = (const float*)d_in[2];
    const float* gs1  = (const float*)d_in[4];
    const float* ts1  = (const float*)d_in[5];
    const float* Ws2  = (const float*)d_in[6];
    const float* gs2  = (const float*)d_in[8];
    const float* ts2  = (const float*)d_in[9];
    const float* Wl1  = (const float*)d_in[10];
    const float* gl1  = (const float*)d_in[12];
    const float* tl1  = (const float*)d_in[13];
    const float* Wl2  = (const float*)d_in[14];
    const float* gl2  = (const float*)d_in[16];
    const float* tl2  = (const float*)d_in[17];
    float* out = (float*)d_out;

    k_prep<<<16, 256>>>(Ws1, Wl1, Ws2, Wl2);
    k_pos<<<NPTS/256, 256>>>(pos);
    k_pack<<<dim3(NN/32, 2, BB), 256>>>(x);
    k_knn1<<<dim3(NN/128, SEG, BB), 128>>>();
    k_knn2<<<NPTS/128, 128>>>();
    k_pq<<<dim3(NPTS/64, 4), 128>>>();

    // short stream (k=6), channels 0..63
    k_stats1<6><<<G_STAT, 256>>>();
    k_reduce<<<1, 256>>>(G_STAT, 1.f/(NPTS*6),  gs1, ts1, 0);
    k_conv2<6><<<G_CONV, 128>>>();
    k_reduce<<<1, 256>>>(G_CONV, 1.f/(NPTS*6),  gs2, ts2, 1);
    k_out<6><<<NPTS/32, 256>>>(out);

    // long stream (k=12), channels 64..127
    k_stats1<12><<<G_STAT, 256>>>();
    k_reduce<<<1, 256>>>(G_STAT, 1.f/(NPTS*12), gl1, tl1, 0);
    k_conv2<12><<<G_CONV, 128>>>();
    k_reduce<<<1, 256>>>(G_CONV, 1.f/(NPTS*12), gl2, tl2, 1);
    k_out<12><<<NPTS/32, 256>>>(out);
}

// round 6
// speedup vs baseline: 4.6710x; 1.0569x over previous
#include <cuda_runtime.h>

#define BB   4
#define NN   8192
#define CCH  64
#define NPTS (BB*NN)          // 32768
#define KLn  12
#define EPSbn 1e-5f
#define G_STAT 1024
#define G_CONV 1184
#define MT   96               // conv2 edge-tile (divisible by 6 and 12)
#define KCH  1024             // knn shared chunk (float4 count)

// ---------------- scratch (static device arrays; no allocation) ----------------
__device__ __align__(16) float  g_xt[NPTS*CCH];            // x transposed (B,N,C)   8MB
__device__ __align__(16) float4 g_pp[NPTS];                // packed points (x,y,z,|p|^2)
__device__             int    g_idx[NPTS*KLn];             // 12 NN per point (sorted)
__device__             float  g_kd[KLn*NPTS];              // unsorted knn dists
__device__             int    g_ki[KLn*NPTS];              // unsorted knn idx
__device__ __align__(16) float g_PQ[4][NPTS*CCH];          // P_s,Q_s,P_l,Q_l        32MB
__device__ __align__(16) float g_mx[NPTS*CCH];             // per-(pt,ch) max of h2   8MB
__device__ __align__(16) float g_mn[NPTS*CCH];             // per-(pt,ch) min of h2   8MB
__device__             float  g_part[2048*128];            // block partial stats
__device__             float  g_bnA[128];                  // layer1 scale/shift
__device__             float  g_bnB[128];                  // layer2 scale/shift
__device__ __align__(16) float g_Wf[4][4096];              // folded conv1 W, [k][o]
__device__ __align__(16) float g_W2t[2][4096];             // conv2 W transposed [k][o]

// ---------------- f32x2 helpers ----------------
__device__ __forceinline__ unsigned long long pk2(float lo, float hi) {
    unsigned long long r;
    asm("mov.b64 %0, {%1,%2};" : "=l"(r) : "f"(lo), "f"(hi));
    return r;
}
__device__ __forceinline__ unsigned long long dup2(float v) { return pk2(v, v); }
__device__ __forceinline__ void upk2(unsigned long long r, float& lo, float& hi) {
    asm("mov.b64 {%0,%1}, %2;" : "=f"(lo), "=f"(hi) : "l"(r));
}
__device__ __forceinline__ unsigned long long ffma2(unsigned long long a,
                                                    unsigned long long b,
                                                    unsigned long long c) {
    unsigned long long d;
    asm("fma.rn.f32x2 %0, %1, %2, %3;" : "=l"(d) : "l"(a), "l"(b), "l"(c));
    return d;
}

// ---------------- weight prep: fold conv1, transpose everything ----------------
__global__ void k_prep(const float* __restrict__ Ws1, const float* __restrict__ Wl1,
                       const float* __restrict__ Ws2, const float* __restrict__ Wl2)
{
    int t = blockIdx.x*blockDim.x + threadIdx.x;
    if (t < 4096) {
        int o = t >> 6, c = t & 63;
        float a0 = Ws1[o*128 + c],  a1 = Ws1[o*128 + 64 + c];
        g_Wf[0][c*64+o] = a0 - a1;          // Wa_s
        g_Wf[1][c*64+o] = a1;               // Wb_s
        float b0 = Wl1[o*128 + c],  b1 = Wl1[o*128 + 64 + c];
        g_Wf[2][c*64+o] = b0 - b1;          // Wa_l
        g_Wf[3][c*64+o] = b1;               // Wb_l
        g_W2t[0][c*64+o] = Ws2[o*64+c];
        g_W2t[1][c*64+o] = Wl2[o*64+c];
    }
}

// ---------------- pack pos into float4 ----------------
__global__ void k_pos(const float* __restrict__ pos)
{
    int t = blockIdx.x*blockDim.x + threadIdx.x;
    if (t < NPTS) {
        int n = t & (NN-1), b = t >> 13;
        float px = pos[(b*3+0)*NN + n];
        float py = pos[(b*3+1)*NN + n];
        float pz = pos[(b*3+2)*NN + n];
        g_pp[t] = make_float4(px, py, pz, px*px + py*py + pz*pz);
    }
}

// ---------------- coalesced tiled transpose of x ----------------
__global__ __launch_bounds__(256) void k_pack(const float* __restrict__ x)
{
    __shared__ float tile[32][33];
    int b  = blockIdx.z;
    int c0 = blockIdx.y * 32;
    int n0 = blockIdx.x * 32;
    int tx = threadIdx.x & 31, ty = threadIdx.x >> 5;   // ty 0..7
#pragma unroll
    for (int i = 0; i < 4; i++) {
        int r = ty + 8*i;                               // channel row
        tile[r][tx] = x[((size_t)(b*CCH + c0 + r))*NN + n0 + tx];
    }
    __syncthreads();
#pragma unroll
    for (int i = 0; i < 4; i++) {
        int r = ty + 8*i;                               // n row
        g_xt[((size_t)(b*NN + n0 + r))*64 + c0 + tx] = tile[tx][r];
    }
}

// ---------------- KNN: full scan, dist-only top-13, then threshold re-scan ----
// Phase A: branch-free FMNMX insertion chain keeps 13 smallest distances.
// Phase B: identical distance recomputation; accept d <= thr, emit (d, idx).
#define KINS(dv)                                                   \
    if ((dv) < bd[12]) {                                           \
        float tt = (dv);                                           \
        _Pragma("unroll")                                          \
        for (int jj = 0; jj < 13; jj++) {                          \
            float lo = fminf(bd[jj], tt);                          \
            tt = fmaxf(bd[jj], tt);                                \
            bd[jj] = lo;                                           \
        }                                                          \
    }

__global__ __launch_bounds__(64) void k_knn1()
{
    __shared__ __align__(16) float4 tile[KCH];   // 16KB chunk
    int q = blockIdx.x*64 + threadIdx.x;
    int b = q >> 13;
    int nself = q & (NN-1);
    float4 qp = g_pp[q];
    float qx = -2.f*qp.x, qy = -2.f*qp.y, qz = -2.f*qp.z;

    float bd[13];
#pragma unroll
    for (int i = 0; i < 13; i++) bd[i] = 3.4e38f;

    // ---- phase A: top-13 distances ----
    for (int cb = 0; cb < NN; cb += KCH) {
        __syncthreads();
        for (int i = threadIdx.x; i < KCH; i += 64)
            tile[i] = g_pp[b*NN + cb + i];
        __syncthreads();
#pragma unroll 1
        for (int c0 = 0; c0 < KCH; c0 += 4) {
            float4 p0 = tile[c0+0], p1 = tile[c0+1];
            float4 p2 = tile[c0+2], p3 = tile[c0+3];
            float d0 = fmaf(qx,p0.x, fmaf(qy,p0.y, fmaf(qz,p0.z, p0.w)));
            float d1 = fmaf(qx,p1.x, fmaf(qy,p1.y, fmaf(qz,p1.z, p1.w)));
            float d2 = fmaf(qx,p2.x, fmaf(qy,p2.y, fmaf(qz,p2.z, p2.w)));
            float d3 = fmaf(qx,p3.x, fmaf(qy,p3.y, fmaf(qz,p3.z, p3.w)));
            float m = fminf(fminf(d0,d1), fminf(d2,d3));
            if (m < bd[12]) {
                KINS(d0); KINS(d1); KINS(d2); KINS(d3);
            }
        }
    }
    float thr = bd[12];

    // ---- phase B: collect indices with d <= thr (excluding self) ----
    int cnt = 0;
    for (int cb = 0; cb < NN; cb += KCH) {
        __syncthreads();
        for (int i = threadIdx.x; i < KCH; i += 64)
            tile[i] = g_pp[b*NN + cb + i];
        __syncthreads();
#pragma unroll 1
        for (int c0 = 0; c0 < KCH; c0 += 4) {
            float4 p0 = tile[c0+0], p1 = tile[c0+1];
            float4 p2 = tile[c0+2], p3 = tile[c0+3];
            float d0 = fmaf(qx,p0.x, fmaf(qy,p0.y, fmaf(qz,p0.z, p0.w)));
            float d1 = fmaf(qx,p1.x, fmaf(qy,p1.y, fmaf(qz,p1.z, p1.w)));
            float d2 = fmaf(qx,p2.x, fmaf(qy,p2.y, fmaf(qz,p2.z, p2.w)));
            float d3 = fmaf(qx,p3.x, fmaf(qy,p3.y, fmaf(qz,p3.z, p3.w)));
            float m = fminf(fminf(d0,d1), fminf(d2,d3));
            if (m <= thr) {
                float dd[4] = {d0, d1, d2, d3};
#pragma unroll
                for (int u = 0; u < 4; u++) {
                    if (dd[u] <= thr) {
                        int j = cb + c0 + u;
                        if (j != nself && cnt < 12) {
                            g_kd[cnt*NPTS + q] = dd[u];
                            g_ki[cnt*NPTS + q] = j;
                            cnt++;
                        }
                    }
                }
            }
        }
    }
}

// ---------------- KNN sort: static 12-element network per point ----------------
__global__ __launch_bounds__(256) void k_knn3()
{
    int q = blockIdx.x*256 + threadIdx.x;
    float d[12]; int ix[12];
#pragma unroll
    for (int r = 0; r < 12; r++) {
        d[r]  = g_kd[r*NPTS + q];
        ix[r] = g_ki[r*NPTS + q];
    }
#pragma unroll
    for (int i = 0; i < 11; i++)
#pragma unroll
        for (int j = 0; j < 11 - i; j++)
            if (d[j+1] < d[j]) {
                float td = d[j]; d[j] = d[j+1]; d[j+1] = td;
                int   ti = ix[j]; ix[j] = ix[j+1]; ix[j+1] = ti;
            }
#pragma unroll
    for (int r = 0; r < 12; r++)
        g_idx[q*KLn + r] = ix[r];
}

// ---------------- P/Q GEMM with f32x2 FMA ----------------
__global__ __launch_bounds__(128) void k_pq()
{
    __shared__ __align__(16) float Ws[4096];
    __shared__ __align__(16) float Us[4096];
    int w = blockIdx.y;
    int t = threadIdx.x;
    for (int i = t; i < 4096; i += 128) Ws[i] = g_Wf[w][i];

    int base = blockIdx.x * 64;
    {   // stage X tile k-major with xor swizzle
        int e = t >> 1, h = t & 1;
        const float4* src = (const float4*)&g_xt[(base + e)*64 + h*32];
        int gg = e >> 2, eo = e & 3;
#pragma unroll
        for (int c4 = 0; c4 < 8; c4++) {
            float4 v = src[c4];
            int c = h*32 + c4*4;
            Us[(c+0)*64 + ((gg ^ ((c+0)&15))<<2) + eo] = v.x;
            Us[(c+1)*64 + ((gg ^ ((c+1)&15))<<2) + eo] = v.y;
            Us[(c+2)*64 + ((gg ^ ((c+2)&15))<<2) + eo] = v.z;
            Us[(c+3)*64 + ((gg ^ ((c+3)&15))<<2) + eo] = v.w;
        }
    }
    __syncthreads();

    int tx = t & 15, ty = t >> 4;
    unsigned long long acc2[4][4];             // [oi-pair][mi]
#pragma unroll
    for (int i = 0; i < 4; i++)
#pragma unroll
        for (int j = 0; j < 4; j++) acc2[i][j] = 0ULL;

#pragma unroll 8
    for (int k = 0; k < 64; k++) {
        const unsigned long long* ap = (const unsigned long long*)&Ws[k*64 + ty*8];
        unsigned long long a2[4] = {ap[0], ap[1], ap[2], ap[3]};
        float4 bf = *(const float4*)&Us[k*64 + ((tx ^ (k&15))<<2)];
        unsigned long long b2[4] = {dup2(bf.x), dup2(bf.y), dup2(bf.z), dup2(bf.w)};
#pragma unroll
        for (int oi = 0; oi < 4; oi++)
#pragma unroll
            for (int mi = 0; mi < 4; mi++)
                acc2[oi][mi] = ffma2(a2[oi], b2[mi], acc2[oi][mi]);
    }

    float* out = g_PQ[w];
#pragma unroll
    for (int mi = 0; mi < 4; mi++) {
        float a[8];
#pragma unroll
        for (int oi = 0; oi < 4; oi++) upk2(acc2[oi][mi], a[2*oi], a[2*oi+1]);
        int pt = base + tx*4 + mi;
        *(float4*)&out[pt*64 + ty*8]     = make_float4(a[0],a[1],a[2],a[3]);
        *(float4*)&out[pt*64 + ty*8 + 4] = make_float4(a[4],a[5],a[6],a[7]);
    }
}

// ---------------- stats of h1 = P[i]+Q[j] over all edges ----------------
template<int K>
__global__ __launch_bounds__(256) void k_stats1()
{
    const float* __restrict__ P = g_PQ[(K==6)?0:2];
    const float* __restrict__ Q = g_PQ[(K==6)?1:3];
    const int M = NPTS*K;
    int warp = threadIdx.x >> 5, lane = threadIdx.x & 31;
    int gw = blockIdx.x*8 + warp, nw = G_STAT*8;
    float s0=0, ss0=0, s1=0, ss1=0;
    for (int m = gw; m < M; m += nw) {
        int kk = m % K, bn = m / K;
        int j  = g_idx[bn*KLn + kk];
        int b  = bn >> 13;
        const float* Pp = &P[bn*64];
        const float* Qp = &Q[(b*NN + j)*64];
        float v0 = Pp[lane]      + Qp[lane];
        float v1 = Pp[lane + 32] + Qp[lane + 32];
        s0 += v0; ss0 = fmaf(v0, v0, ss0);
        s1 += v1; ss1 = fmaf(v1, v1, ss1);
    }
    __shared__ float stg[8][128];
    stg[warp][lane]      = s0;  stg[warp][64+lane] = ss0;
    stg[warp][32+lane]   = s1;  stg[warp][96+lane] = ss1;
    __syncthreads();
    int t = threadIdx.x;
    if (t < 128) {
        float a = 0;
#pragma unroll
        for (int w2 = 0; w2 < 8; w2++) a += stg[w2][t];
        g_part[blockIdx.x*128 + t] = a;
    }
}

// ---------------- finalize BN params (parallel, deterministic) ----------------
__global__ __launch_bounds__(256) void k_reduce(int G, float invM,
                         const float* __restrict__ gamma,
                         const float* __restrict__ beta, int which)
{
    __shared__ float sm[8][64];
    int t = threadIdx.x;
    int c = t & 63, grp = t >> 6;              // 4 groups
    int chunk = (G + 3) >> 2;
    int g0 = grp*chunk, g1 = min(G, g0 + chunk);
    float S = 0.f, SS = 0.f;
    for (int g = g0; g < g1; g++) { S += g_part[g*128 + c]; SS += g_part[g*128 + 64 + c]; }
    sm[grp][c] = S; sm[4+grp][c] = SS;
    __syncthreads();
    if (t < 64) {
        float Sa = 0.f, SSa = 0.f;
#pragma unroll
        for (int g = 0; g < 4; g++) { Sa += sm[g][t]; SSa += sm[4+g][t]; }
        float mean = Sa * invM;
        float var  = SSa * invM - mean*mean;
        float sc   = gamma[t] * rsqrtf(var + EPSbn);
        float sh   = beta[t] - mean*sc;
        float* dst = which ? g_bnB : g_bnA;
        dst[t] = sc; dst[64+t] = sh;
    }
}

// ---------------- conv2: 96-edge tiles, f32x2 GEMM, fused min/max over k ----------------
template<int K>
__global__ __launch_bounds__(128) void k_conv2()
{
    const float* __restrict__ P   = g_PQ[(K==6)?0:2];
    const float* __restrict__ Q   = g_PQ[(K==6)?1:3];
    const float* __restrict__ W2t = g_W2t[(K==6)?0:1];
    const int nTiles = (NPTS*K)/MT;
    const int PPT = MT/K;                      // whole points per tile

    __shared__ __align__(16) float Ws[4096];
    __shared__ __align__(16) float Ub[6336];   // union: Us 64x97 / h2s 96x66
    __shared__ float bnsc[64], bnsh[64];
    __shared__ float blockS[64], blockSS[64];
    int t = threadIdx.x;
    for (int i = t; i < 4096; i += 128) Ws[i] = W2t[i];
    if (t < 64) { bnsc[t] = g_bnA[t]; bnsh[t] = g_bnA[64+t]; }
    __syncthreads();

    int tx = t & 15, ty = t >> 4;
    float accS[8], accSS[8];
#pragma unroll
    for (int i = 0; i < 8; i++) { accS[i] = 0.f; accSS[i] = 0.f; }

    for (int tile = blockIdx.x; tile < nTiles; tile += G_CONV) {
        int mbase = tile * MT;
        __syncthreads();                       // Ub reuse guard
        // gather + BN1 + ReLU -> Us (k-major, row stride 97)
        for (int u = t; u < 2*MT; u += 128) {
            int e = u >> 1, h = u & 1;
            int m = mbase + e;
            int kk = m % K, bn = m / K;
            int j  = g_idx[bn*KLn + kk];
            int b  = bn >> 13;
            const float4* Pp = (const float4*)&P[bn*64 + h*32];
            const float4* Qp = (const float4*)&Q[(b*NN + j)*64 + h*32];
#pragma unroll
            for (int c4 = 0; c4 < 8; c4++) {
                float4 pv = Pp[c4], qv = Qp[c4];
                int c = h*32 + c4*4;
                Ub[(c+0)*97 + e] = fmaxf(0.f, fmaf(pv.x+qv.x, bnsc[c+0], bnsh[c+0]));
                Ub[(c+1)*97 + e] = fmaxf(0.f, fmaf(pv.y+qv.y, bnsc[c+1], bnsh[c+1]));
                Ub[(c+2)*97 + e] = fmaxf(0.f, fmaf(pv.z+qv.z, bnsc[c+2], bnsh[c+2]));
                Ub[(c+3)*97 + e] = fmaxf(0.f, fmaf(pv.w+qv.w, bnsc[c+3], bnsh[c+3]));
            }
        }
        __syncthreads();

        // GEMM: edges e = tx + 16*mi (mi<6), channels ty*8..ty*8+7 (as 4 pairs)
        unsigned long long acc2[4][6];
#pragma unroll
        for (int i = 0; i < 4; i++)
#pragma unroll
            for (int j2 = 0; j2 < 6; j2++) acc2[i][j2] = 0ULL;

#pragma unroll 8
        for (int k = 0; k < 64; k++) {
            const unsigned long long* ap = (const unsigned long long*)&Ws[k*64 + ty*8];
            unsigned long long a2[4] = {ap[0], ap[1], ap[2], ap[3]};
            unsigned long long b2[6];
#pragma unroll
            for (int mi = 0; mi < 6; mi++)
                b2[mi] = dup2(Ub[k*97 + tx + 16*mi]);
#pragma unroll
            for (int oi = 0; oi < 4; oi++)
#pragma unroll
                for (int mi = 0; mi < 6; mi++)
                    acc2[oi][mi] = ffma2(a2[oi], b2[mi], acc2[oi][mi]);
        }
        __syncthreads();                       // Us dead; reuse Ub for h2s

        // unpack: stats accumulation + write h2 tile to shared (row stride 66)
#pragma unroll
        for (int mi = 0; mi < 6; mi++) {
            int e = tx + 16*mi;
            float v[8];
#pragma unroll
            for (int oi = 0; oi < 4; oi++) upk2(acc2[oi][mi], v[2*oi], v[2*oi+1]);
#pragma unroll
            for (int oi = 0; oi < 8; oi++) {
                accS[oi]  += v[oi];
                accSS[oi] = fmaf(v[oi], v[oi], accSS[oi]);
            }
#pragma unroll
            for (int oi = 0; oi < 4; oi++)
                *(float2*)&Ub[e*66 + ty*8 + 2*oi] = make_float2(v[2*oi], v[2*oi+1]);
        }
        __syncthreads();

        // per-(point,channel) min/max over K edges (tile holds whole points)
        for (int s = t; s < PPT*64; s += 128) {
            int p = s >> 6, ch = s & 63;
            float vmax = -3.4e38f, vmin = 3.4e38f;
#pragma unroll
            for (int kk = 0; kk < K; kk++) {
                float v = Ub[(p*K + kk)*66 + ch];
                vmax = fmaxf(vmax, v); vmin = fminf(vmin, v);
            }
            int pt = mbase/K + p;
            g_mx[pt*64 + ch] = vmax;
            g_mn[pt*64 + ch] = vmin;
        }
    }

    // cross-thread stats reduce over tx lanes
#pragma unroll
    for (int off = 1; off < 16; off <<= 1)
#pragma unroll
        for (int oi = 0; oi < 8; oi++) {
            accS[oi]  += __shfl_xor_sync(0xffffffffu, accS[oi],  off);
            accSS[oi] += __shfl_xor_sync(0xffffffffu, accSS[oi], off);
        }
    if (tx == 0)
#pragma unroll
        for (int oi = 0; oi < 8; oi++) { blockS[ty*8+oi] = accS[oi]; blockSS[ty*8+oi] = accSS[oi]; }
    __syncthreads();
    if (t < 128)
        g_part[blockIdx.x*128 + t] = (t < 64) ? blockS[t] : blockSS[t-64];
}

// ---------------- BN2 + ReLU + max -> output (from min/max buffers) ----------------
template<int K>
__global__ __launch_bounds__(256) void k_out(float* __restrict__ out)
{
    const int chOff = (K==6) ? 0 : 64;
    __shared__ float res[64][33];
    int t = threadIdx.x;
    int warp = t >> 5, lane = t & 31;
    int bn0 = blockIdx.x * 32;
    int b = bn0 >> 13, n0 = bn0 & (NN-1);
    float sc0 = g_bnB[lane],      sh0 = g_bnB[64+lane];
    float sc1 = g_bnB[lane + 32], sh1 = g_bnB[96+lane];
#pragma unroll
    for (int i = 0; i < 4; i++) {
        int nl = warp*4 + i;
        int pt = bn0 + nl;
        float h0 = (sc0 >= 0.f) ? g_mx[pt*64 + lane]      : g_mn[pt*64 + lane];
        float h1 = (sc1 >= 0.f) ? g_mx[pt*64 + lane + 32] : g_mn[pt*64 + lane + 32];
        res[lane][nl]      = fmaxf(0.f, fmaf(h0, sc0, sh0));
        res[lane + 32][nl] = fmaxf(0.f, fmaf(h1, sc1, sh1));
    }
    __syncthreads();
#pragma unroll
    for (int i = 0; i < 8; i++) {
        int id = t + i*256;
        int r = id >> 5, col = id & 31;
        out[((size_t)b*128 + chOff + r)*NN + n0 + col] = res[r][col];
    }
}

// ---------------- launch ----------------
extern "C" void kernel_launch(void* const* d_in, const int* in_sizes, int n_in,
                              void* d_out, int out_size)
{
    const float* x    = (const float*)d_in[0];
    const float* pos  = (const float*)d_in[1];
    const float* Ws1  = (const float*)d_in[2];
    const float* gs1  = (const float*)d_in[4];
    const float* ts1  = (const float*)d_in[5];
    const float* Ws2  = (const float*)d_in[6];
    const float* gs2  = (const float*)d_in[8];
    const float* ts2  = (const float*)d_in[9];
    const float* Wl1  = (const float*)d_in[10];
    const float* gl1  = (const float*)d_in[12];
    const float* tl1  = (const float*)d_in[13];
    const float* Wl2  = (const float*)d_in[14];
    const float* gl2  = (const float*)d_in[16];
    const float* tl2  = (const float*)d_in[17];
    float* out = (float*)d_out;

    k_prep<<<16, 256>>>(Ws1, Wl1, Ws2, Wl2);
    k_pos<<<NPTS/256, 256>>>(pos);
    k_pack<<<dim3(NN/32, 2, BB), 256>>>(x);
    k_knn1<<<NPTS/64, 64>>>();
    k_knn3<<<NPTS/256, 256>>>();
    k_pq<<<dim3(NPTS/64, 4), 128>>>();

    // short stream (k=6), channels 0..63
    k_stats1<6><<<G_STAT, 256>>>();
    k_reduce<<<1, 256>>>(G_STAT, 1.f/(NPTS*6),  gs1, ts1, 0);
    k_conv2<6><<<G_CONV, 128>>>();
    k_reduce<<<1, 256>>>(G_CONV, 1.f/(NPTS*6),  gs2, ts2, 1);
    k_out<6><<<NPTS/32, 256>>>(out);

    // long stream (k=12), channels 64..127
    k_stats1<12><<<G_STAT, 256>>>();
    k_reduce<<<1, 256>>>(G_STAT, 1.f/(NPTS*12), gl1, tl1, 0);
    k_conv2<12><<<G_CONV, 128>>>();
    k_reduce<<<1, 256>>>(G_CONV, 1.f/(NPTS*12), gl2, tl2, 1);
    k_out<12><<<NPTS/32, 256>>>(out);
}

// round 7
// speedup vs baseline: 5.2881x; 1.1321x over previous
#include <cuda_runtime.h>

#define BB   4
#define NN   8192
#define CCH  64
#define NPTS (BB*NN)          // 32768
#define KLn  12
#define EPSbn 1e-5f
#define G_STAT 1024
#define G_CONV 1184
#define MT   96               // conv2 edge-tile (divisible by 6 and 12)
#define KCH  1024             // knn shared chunk (float4 count)
#define HALFN 4096            // candidates per knn thread (TPQ=2)

// ---------------- scratch (static device arrays; no allocation) ----------------
__device__ __align__(16) float  g_xt[NPTS*CCH];            // x transposed (B,N,C)   8MB
__device__ __align__(16) float4 g_pp[NPTS];                // packed points (x,y,z,|p|^2)
__device__             int    g_idx[NPTS*KLn];             // 12 NN per point (sorted)
__device__ __align__(16) unsigned long long g_kk[26*NPTS]; // packed (d,idx) keys, 2x13 slots
__device__ __align__(16) float g_PQ[4][NPTS*CCH];          // P_s,Q_s,P_l,Q_l        32MB
__device__ __align__(16) float g_mx[NPTS*CCH];             // per-(pt,ch) max of h2   8MB
__device__ __align__(16) float g_mn[NPTS*CCH];             // per-(pt,ch) min of h2   8MB
__device__             float  g_part[2048*128];            // block partial stats
__device__             float  g_bnA[128];                  // layer1 scale/shift
__device__             float  g_bnB[128];                  // layer2 scale/shift
__device__ __align__(16) float g_Wf[4][4096];              // folded conv1 W, [k][o]
__device__ __align__(16) float g_W2t[2][4096];             // conv2 W transposed [k][o]

// ---------------- f32x2 helpers ----------------
__device__ __forceinline__ unsigned long long pk2(float lo, float hi) {
    unsigned long long r;
    asm("mov.b64 %0, {%1,%2};" : "=l"(r) : "f"(lo), "f"(hi));
    return r;
}
__device__ __forceinline__ unsigned long long dup2(float v) { return pk2(v, v); }
__device__ __forceinline__ void upk2(unsigned long long r, float& lo, float& hi) {
    asm("mov.b64 {%0,%1}, %2;" : "=f"(lo), "=f"(hi) : "l"(r));
}
__device__ __forceinline__ unsigned long long ffma2(unsigned long long a,
                                                    unsigned long long b,
                                                    unsigned long long c) {
    unsigned long long d;
    asm("fma.rn.f32x2 %0, %1, %2, %3;" : "=l"(d) : "l"(a), "l"(b), "l"(c));
    return d;
}

// monotone float->u32 (total order preserving, handles negatives)
__device__ __forceinline__ unsigned fmono(float f) {
    unsigned u = __float_as_uint(f);
    return u ^ ((u >> 31) ? 0xFFFFFFFFu : 0x80000000u);
}

// ---------------- weight prep: fold conv1, transpose everything ----------------
__global__ void k_prep(const float* __restrict__ Ws1, const float* __restrict__ Wl1,
                       const float* __restrict__ Ws2, const float* __restrict__ Wl2)
{
    int t = blockIdx.x*blockDim.x + threadIdx.x;
    if (t < 4096) {
        int o = t >> 6, c = t & 63;
        float a0 = Ws1[o*128 + c],  a1 = Ws1[o*128 + 64 + c];
        g_Wf[0][c*64+o] = a0 - a1;          // Wa_s
        g_Wf[1][c*64+o] = a1;               // Wb_s
        float b0 = Wl1[o*128 + c],  b1 = Wl1[o*128 + 64 + c];
        g_Wf[2][c*64+o] = b0 - b1;          // Wa_l
        g_Wf[3][c*64+o] = b1;               // Wb_l
        g_W2t[0][c*64+o] = Ws2[o*64+c];
        g_W2t[1][c*64+o] = Wl2[o*64+c];
    }
}

// ---------------- pack pos into float4 ----------------
__global__ void k_pos(const float* __restrict__ pos)
{
    int t = blockIdx.x*blockDim.x + threadIdx.x;
    if (t < NPTS) {
        int n = t & (NN-1), b = t >> 13;
        float px = pos[(b*3+0)*NN + n];
        float py = pos[(b*3+1)*NN + n];
        float pz = pos[(b*3+2)*NN + n];
        g_pp[t] = make_float4(px, py, pz, px*px + py*py + pz*pz);
    }
}

// ---------------- coalesced tiled transpose of x ----------------
__global__ __launch_bounds__(256) void k_pack(const float* __restrict__ x)
{
    __shared__ float tile[32][33];
    int b  = blockIdx.z;
    int c0 = blockIdx.y * 32;
    int n0 = blockIdx.x * 32;
    int tx = threadIdx.x & 31, ty = threadIdx.x >> 5;   // ty 0..7
#pragma unroll
    for (int i = 0; i < 4; i++) {
        int r = ty + 8*i;                               // channel row
        tile[r][tx] = x[((size_t)(b*CCH + c0 + r))*NN + n0 + tx];
    }
    __syncthreads();
#pragma unroll
    for (int i = 0; i < 4; i++) {
        int r = ty + 8*i;                               // n row
        g_xt[((size_t)(b*NN + n0 + r))*64 + c0 + tx] = tile[tx][r];
    }
}

// ---------------- KNN, TPQ=2: each thread scans half the candidates ----------
// Phase A: branch-free FMNMX chain keeps the 13 smallest dists (sorted).
// Merge:   merge-path of the two sorted half-lists -> global 13th value (thr).
// Phase B: identical distance recomputation; accept d <= thr, emit u64 keys.
#define KINS(dv)                                                   \
    if ((dv) < bd[12]) {                                           \
        float tt = (dv);                                           \
        _Pragma("unroll")                                          \
        for (int jj = 0; jj < 13; jj++) {                          \
            float lo = fminf(bd[jj], tt);                          \
            tt = fmaxf(bd[jj], tt);                                \
            bd[jj] = lo;                                           \
        }                                                          \
    }

__global__ __launch_bounds__(128) void k_knn1()
{
    __shared__ __align__(16) float4 tA[KCH];     // tile for lower-half threads
    __shared__ __align__(16) float4 tB[KCH];     // tile for upper-half threads
    __shared__ float sA[128*13];                 // per-thread sorted top-13
    __shared__ float thrS[64];

    int t  = threadIdx.x;
    int ql = t & 63;                             // query within block
    int h  = t >> 6;                             // half 0/1 (uniform per warp)
    int q  = blockIdx.x*64 + ql;
    int b  = q >> 13;
    int nself = q & (NN-1);
    float4 qp = g_pp[q];
    float qx = -2.f*qp.x, qy = -2.f*qp.y, qz = -2.f*qp.z;
    float4* tile = h ? tB : tA;
    int hbase = b*NN + h*HALFN;

    float bd[13];
#pragma unroll
    for (int i = 0; i < 13; i++) bd[i] = 3.4e38f;

    // ---- phase A: per-half top-13 distances ----
    for (int cb = 0; cb < HALFN; cb += KCH) {
        __syncthreads();
        for (int i = ql; i < KCH; i += 64)
            tile[i] = g_pp[hbase + cb + i];
        __syncthreads();
#pragma unroll 1
        for (int c0 = 0; c0 < KCH; c0 += 8) {
            float d[8];
#pragma unroll
            for (int u = 0; u < 8; u++) {
                float4 p = tile[c0+u];
                d[u] = fmaf(qx,p.x, fmaf(qy,p.y, fmaf(qz,p.z, p.w)));
            }
            float m = fminf(fminf(fminf(d[0],d[1]), fminf(d[2],d[3])),
                            fminf(fminf(d[4],d[5]), fminf(d[6],d[7])));
            if (m < bd[12]) {
                KINS(d[0]); KINS(d[1]); KINS(d[2]); KINS(d[3]);
                KINS(d[4]); KINS(d[5]); KINS(d[6]); KINS(d[7]);
            }
        }
    }

    // ---- publish sorted half-lists, merge-path to global 13th (thr) ----
#pragma unroll
    for (int r = 0; r < 13; r++) sA[t*13 + r] = bd[r];
    __syncthreads();
    if (t < 64) {
        const float* A = &sA[t*13];
        const float* Bv = &sA[(t+64)*13];
        int i = 0, j = 0; float v = 0.f;
#pragma unroll
        for (int s = 0; s < 13; s++) {
            float a = A[i], bb = Bv[j];
            if (a <= bb) { v = a; i++; } else { v = bb; j++; }
        }
        thrS[t] = v;
    }
    __syncthreads();
    float thr = thrS[ql];

    // ---- phase B: emit u64 keys for d <= thr, excluding self ----
    int cnt = 0;
    for (int cb = 0; cb < HALFN; cb += KCH) {
        __syncthreads();
        for (int i = ql; i < KCH; i += 64)
            tile[i] = g_pp[hbase + cb + i];
        __syncthreads();
#pragma unroll 1
        for (int c0 = 0; c0 < KCH; c0 += 8) {
            float d[8];
#pragma unroll
            for (int u = 0; u < 8; u++) {
                float4 p = tile[c0+u];
                d[u] = fmaf(qx,p.x, fmaf(qy,p.y, fmaf(qz,p.z, p.w)));
            }
            float m = fminf(fminf(fminf(d[0],d[1]), fminf(d[2],d[3])),
                            fminf(fminf(d[4],d[5]), fminf(d[6],d[7])));
            if (m <= thr) {
#pragma unroll
                for (int u = 0; u < 8; u++) {
                    if (d[u] <= thr) {
                        int j = h*HALFN + cb + c0 + u;
                        if (j != nself && cnt < 13) {
                            unsigned long long key =
                                ((unsigned long long)fmono(d[u]) << 13) | (unsigned)j;
                            g_kk[(h*13 + cnt)*NPTS + q] = key;
                            cnt++;
                        }
                    }
                }
            }
        }
    }
#pragma unroll 1
    for (int r = cnt; r < 13; r++)
        g_kk[(h*13 + r)*NPTS + q] = ~0ULL;     // pad
}

// ---------------- KNN select+sort: 12 smallest of 26 keys per query --------
__global__ __launch_bounds__(256) void k_knn3()
{
    int q = blockIdx.x*256 + threadIdx.x;
    unsigned long long best[12];
#pragma unroll
    for (int r = 0; r < 12; r++) best[r] = ~0ULL;
#pragma unroll 1
    for (int r = 0; r < 26; r++) {
        unsigned long long key = g_kk[r*NPTS + q];
        if (key < best[11]) {
            unsigned long long tt = key;
#pragma unroll
            for (int j = 0; j < 12; j++) {
                unsigned long long lo = (best[j] < tt) ? best[j] : tt;
                unsigned long long hi = (best[j] < tt) ? tt : best[j];
                best[j] = lo; tt = hi;
            }
        }
    }
#pragma unroll
    for (int r = 0; r < 12; r++)
        g_idx[q*KLn + r] = (int)(best[r] & 8191u);
}

// ---------------- P/Q GEMM with f32x2 FMA ----------------
__global__ __launch_bounds__(128) void k_pq()
{
    __shared__ __align__(16) float Ws[4096];
    __shared__ __align__(16) float Us[4096];
    int w = blockIdx.y;
    int t = threadIdx.x;
    for (int i = t; i < 4096; i += 128) Ws[i] = g_Wf[w][i];

    int base = blockIdx.x * 64;
    {   // stage X tile k-major with xor swizzle
        int e = t >> 1, h = t & 1;
        const float4* src = (const float4*)&g_xt[(base + e)*64 + h*32];
        int gg = e >> 2, eo = e & 3;
#pragma unroll
        for (int c4 = 0; c4 < 8; c4++) {
            float4 v = src[c4];
            int c = h*32 + c4*4;
            Us[(c+0)*64 + ((gg ^ ((c+0)&15))<<2) + eo] = v.x;
            Us[(c+1)*64 + ((gg ^ ((c+1)&15))<<2) + eo] = v.y;
            Us[(c+2)*64 + ((gg ^ ((c+2)&15))<<2) + eo] = v.z;
            Us[(c+3)*64 + ((gg ^ ((c+3)&15))<<2) + eo] = v.w;
        }
    }
    __syncthreads();

    int tx = t & 15, ty = t >> 4;
    unsigned long long acc2[4][4];             // [oi-pair][mi]
#pragma unroll
    for (int i = 0; i < 4; i++)
#pragma unroll
        for (int j = 0; j < 4; j++) acc2[i][j] = 0ULL;

#pragma unroll 8
    for (int k = 0; k < 64; k++) {
        const unsigned long long* ap = (const unsigned long long*)&Ws[k*64 + ty*8];
        unsigned long long a2[4] = {ap[0], ap[1], ap[2], ap[3]};
        float4 bf = *(const float4*)&Us[k*64 + ((tx ^ (k&15))<<2)];
        unsigned long long b2[4] = {dup2(bf.x), dup2(bf.y), dup2(bf.z), dup2(bf.w)};
#pragma unroll
        for (int oi = 0; oi < 4; oi++)
#pragma unroll
            for (int mi = 0; mi < 4; mi++)
                acc2[oi][mi] = ffma2(a2[oi], b2[mi], acc2[oi][mi]);
    }

    float* out = g_PQ[w];
#pragma unroll
    for (int mi = 0; mi < 4; mi++) {
        float a[8];
#pragma unroll
        for (int oi = 0; oi < 4; oi++) upk2(acc2[oi][mi], a[2*oi], a[2*oi+1]);
        int pt = base + tx*4 + mi;
        *(float4*)&out[pt*64 + ty*8]     = make_float4(a[0],a[1],a[2],a[3]);
        *(float4*)&out[pt*64 + ty*8 + 4] = make_float4(a[4],a[5],a[6],a[7]);
    }
}

// ---------------- stats of h1 = P[i]+Q[j] over all edges ----------------
template<int K>
__global__ __launch_bounds__(256) void k_stats1()
{
    const float* __restrict__ P = g_PQ[(K==6)?0:2];
    const float* __restrict__ Q = g_PQ[(K==6)?1:3];
    const int M = NPTS*K;
    int warp = threadIdx.x >> 5, lane = threadIdx.x & 31;
    int gw = blockIdx.x*8 + warp, nw = G_STAT*8;
    float s0=0, ss0=0, s1=0, ss1=0;
    for (int m = gw; m < M; m += nw) {
        int kk = m % K, bn = m / K;
        int j  = g_idx[bn*KLn + kk];
        int b  = bn >> 13;
        const float* Pp = &P[bn*64];
        const float* Qp = &Q[(b*NN + j)*64];
        float v0 = Pp[lane]      + Qp[lane];
        float v1 = Pp[lane + 32] + Qp[lane + 32];
        s0 += v0; ss0 = fmaf(v0, v0, ss0);
        s1 += v1; ss1 = fmaf(v1, v1, ss1);
    }
    __shared__ float stg[8][128];
    stg[warp][lane]      = s0;  stg[warp][64+lane] = ss0;
    stg[warp][32+lane]   = s1;  stg[warp][96+lane] = ss1;
    __syncthreads();
    int t = threadIdx.x;
    if (t < 128) {
        float a = 0;
#pragma unroll
        for (int w2 = 0; w2 < 8; w2++) a += stg[w2][t];
        g_part[blockIdx.x*128 + t] = a;
    }
}

// ---------------- finalize BN params (parallel, deterministic) ----------------
__global__ __launch_bounds__(256) void k_reduce(int G, float invM,
                         const float* __restrict__ gamma,
                         const float* __restrict__ beta, int which)
{
    __shared__ float sm[8][64];
    int t = threadIdx.x;
    int c = t & 63, grp = t >> 6;              // 4 groups
    int chunk = (G + 3) >> 2;
    int g0 = grp*chunk, g1 = min(G, g0 + chunk);
    float S = 0.f, SS = 0.f;
    for (int g = g0; g < g1; g++) { S += g_part[g*128 + c]; SS += g_part[g*128 + 64 + c]; }
    sm[grp][c] = S; sm[4+grp][c] = SS;
    __syncthreads();
    if (t < 64) {
        float Sa = 0.f, SSa = 0.f;
#pragma unroll
        for (int g = 0; g < 4; g++) { Sa += sm[g][t]; SSa += sm[4+g][t]; }
        float mean = Sa * invM;
        float var  = SSa * invM - mean*mean;
        float sc   = gamma[t] * rsqrtf(var + EPSbn);
        float sh   = beta[t] - mean*sc;
        float* dst = which ? g_bnB : g_bnA;
        dst[t] = sc; dst[64+t] = sh;
    }
}

// ---------------- conv2: 96-edge tiles, f32x2 GEMM, fused min/max over k ----------------
template<int K>
__global__ __launch_bounds__(128) void k_conv2()
{
    const float* __restrict__ P   = g_PQ[(K==6)?0:2];
    const float* __restrict__ Q   = g_PQ[(K==6)?1:3];
    const float* __restrict__ W2t = g_W2t[(K==6)?0:1];
    const int nTiles = (NPTS*K)/MT;
    const int PPT = MT/K;                      // whole points per tile

    __shared__ __align__(16) float Ws[4096];
    __shared__ __align__(16) float Ub[6336];   // union: Us 64x97 / h2s 96x66
    __shared__ float bnsc[64], bnsh[64];
    __shared__ float blockS[64], blockSS[64];
    int t = threadIdx.x;
    for (int i = t; i < 4096; i += 128) Ws[i] = W2t[i];
    if (t < 64) { bnsc[t] = g_bnA[t]; bnsh[t] = g_bnA[64+t]; }
    __syncthreads();

    int tx = t & 15, ty = t >> 4;
    float accS[8], accSS[8];
#pragma unroll
    for (int i = 0; i < 8; i++) { accS[i] = 0.f; accSS[i] = 0.f; }

    for (int tile = blockIdx.x; tile < nTiles; tile += G_CONV) {
        int mbase = tile * MT;
        __syncthreads();                       // Ub reuse guard
        // gather + BN1 + ReLU -> Us (k-major, row stride 97)
        for (int u = t; u < 2*MT; u += 128) {
            int e = u >> 1, h = u & 1;
            int m = mbase + e;
            int kk = m % K, bn = m / K;
            int j  = g_idx[bn*KLn + kk];
            int b  = bn >> 13;
            const float4* Pp = (const float4*)&P[bn*64 + h*32];
            const float4* Qp = (const float4*)&Q[(b*NN + j)*64 + h*32];
#pragma unroll
            for (int c4 = 0; c4 < 8; c4++) {
                float4 pv = Pp[c4], qv = Qp[c4];
                int c = h*32 + c4*4;
                Ub[(c+0)*97 + e] = fmaxf(0.f, fmaf(pv.x+qv.x, bnsc[c+0], bnsh[c+0]));
                Ub[(c+1)*97 + e] = fmaxf(0.f, fmaf(pv.y+qv.y, bnsc[c+1], bnsh[c+1]));
                Ub[(c+2)*97 + e] = fmaxf(0.f, fmaf(pv.z+qv.z, bnsc[c+2], bnsh[c+2]));
                Ub[(c+3)*97 + e] = fmaxf(0.f, fmaf(pv.w+qv.w, bnsc[c+3], bnsh[c+3]));
            }
        }
        __syncthreads();

        // GEMM: edges e = tx + 16*mi (mi<6), channels ty*8..ty*8+7 (as 4 pairs)
        unsigned long long acc2[4][6];
#pragma unroll
        for (int i = 0; i < 4; i++)
#pragma unroll
            for (int j2 = 0; j2 < 6; j2++) acc2[i][j2] = 0ULL;

#pragma unroll 8
        for (int k = 0; k < 64; k++) {
            const unsigned long long* ap = (const unsigned long long*)&Ws[k*64 + ty*8];
            unsigned long long a2[4] = {ap[0], ap[1], ap[2], ap[3]};
            unsigned long long b2[6];
#pragma unroll
            for (int mi = 0; mi < 6; mi++)
                b2[mi] = dup2(Ub[k*97 + tx + 16*mi]);
#pragma unroll
            for (int oi = 0; oi < 4; oi++)
#pragma unroll
                for (int mi = 0; mi < 6; mi++)
                    acc2[oi][mi] = ffma2(a2[oi], b2[mi], acc2[oi][mi]);
        }
        __syncthreads();                       // Us dead; reuse Ub for h2s

        // unpack: stats accumulation + write h2 tile to shared (row stride 66)
#pragma unroll
        for (int mi = 0; mi < 6; mi++) {
            int e = tx + 16*mi;
            float v[8];
#pragma unroll
            for (int oi = 0; oi < 4; oi++) upk2(acc2[oi][mi], v[2*oi], v[2*oi+1]);
#pragma unroll
            for (int oi = 0; oi < 8; oi++) {
                accS[oi]  += v[oi];
                accSS[oi] = fmaf(v[oi], v[oi], accSS[oi]);
            }
#pragma unroll
            for (int oi = 0; oi < 4; oi++)
                *(float2*)&Ub[e*66 + ty*8 + 2*oi] = make_float2(v[2*oi], v[2*oi+1]);
        }
        __syncthreads();

        // per-(point,channel) min/max over K edges (tile holds whole points)
        for (int s = t; s < PPT*64; s += 128) {
            int p = s >> 6, ch = s & 63;
            float vmax = -3.4e38f, vmin = 3.4e38f;
#pragma unroll
            for (int kk = 0; kk < K; kk++) {
                float v = Ub[(p*K + kk)*66 + ch];
                vmax = fmaxf(vmax, v); vmin = fminf(vmin, v);
            }
            int pt = mbase/K + p;
            g_mx[pt*64 + ch] = vmax;
            g_mn[pt*64 + ch] = vmin;
        }
    }

    // cross-thread stats reduce over tx lanes
#pragma unroll
    for (int off = 1; off < 16; off <<= 1)
#pragma unroll
        for (int oi = 0; oi < 8; oi++) {
            accS[oi]  += __shfl_xor_sync(0xffffffffu, accS[oi],  off);
            accSS[oi] += __shfl_xor_sync(0xffffffffu, accSS[oi], off);
        }
    if (tx == 0)
#pragma unroll
        for (int oi = 0; oi < 8; oi++) { blockS[ty*8+oi] = accS[oi]; blockSS[ty*8+oi] = accSS[oi]; }
    __syncthreads();
    if (t < 128)
        g_part[blockIdx.x*128 + t] = (t < 64) ? blockS[t] : blockSS[t-64];
}

// ---------------- BN2 + ReLU + max -> output (from min/max buffers) ----------------
template<int K>
__global__ __launch_bounds__(256) void k_out(float* __restrict__ out)
{
    const int chOff = (K==6) ? 0 : 64;
    __shared__ float res[64][33];
    int t = threadIdx.x;
    int warp = t >> 5, lane = t & 31;
    int bn0 = blockIdx.x * 32;
    int b = bn0 >> 13, n0 = bn0 & (NN-1);
    float sc0 = g_bnB[lane],      sh0 = g_bnB[64+lane];
    float sc1 = g_bnB[lane + 32], sh1 = g_bnB[96+lane];
#pragma unroll
    for (int i = 0; i < 4; i++) {
        int nl = warp*4 + i;
        int pt = bn0 + nl;
        float h0 = (sc0 >= 0.f) ? g_mx[pt*64 + lane]      : g_mn[pt*64 + lane];
        float h1 = (sc1 >= 0.f) ? g_mx[pt*64 + lane + 32] : g_mn[pt*64 + lane + 32];
        res[lane][nl]      = fmaxf(0.f, fmaf(h0, sc0, sh0));
        res[lane + 32][nl] = fmaxf(0.f, fmaf(h1, sc1, sh1));
    }
    __syncthreads();
#pragma unroll
    for (int i = 0; i < 8; i++) {
        int id = t + i*256;
        int r = id >> 5, col = id & 31;
        out[((size_t)b*128 + chOff + r)*NN + n0 + col] = res[r][col];
    }
}

// ---------------- launch ----------------
extern "C" void kernel_launch(void* const* d_in, const int* in_sizes, int n_in,
                              void* d_out, int out_size)
{
    const float* x    = (const float*)d_in[0];
    const float* pos  = (const float*)d_in[1];
    const float* Ws1  = (const float*)d_in[2];
    const float* gs1  = (const float*)d_in[4];
    const float* ts1  = (const float*)d_in[5];
    const float* Ws2  = (const float*)d_in[6];
    const float* gs2  = (const float*)d_in[8];
    const float* ts2  = (const float*)d_in[9];
    const float* Wl1  = (const float*)d_in[10];
    const float* gl1  = (const float*)d_in[12];
    const float* tl1  = (const float*)d_in[13];
    const float* Wl2  = (const float*)d_in[14];
    const float* gl2  = (const float*)d_in[16];
    const float* tl2  = (const float*)d_in[17];
    float* out = (float*)d_out;

    k_prep<<<16, 256>>>(Ws1, Wl1, Ws2, Wl2);
    k_pos<<<NPTS/256, 256>>>(pos);
    k_pack<<<dim3(NN/32, 2, BB), 256>>>(x);
    k_knn1<<<NPTS/64, 128>>>();
    k_knn3<<<NPTS/256, 256>>>();
    k_pq<<<dim3(NPTS/64, 4), 128>>>();

    // short stream (k=6), channels 0..63
    k_stats1<6><<<G_STAT, 256>>>();
    k_reduce<<<1, 256>>>(G_STAT, 1.f/(NPTS*6),  gs1, ts1, 0);
    k_conv2<6><<<G_CONV, 128>>>();
    k_reduce<<<1, 256>>>(G_CONV, 1.f/(NPTS*6),  gs2, ts2, 1);
    k_out<6><<<NPTS/32, 256>>>(out);

    // long stream (k=12), channels 64..127
    k_stats1<12><<<G_STAT, 256>>>();
    k_reduce<<<1, 256>>>(G_STAT, 1.f/(NPTS*12), gl1, tl1, 0);
    k_conv2<12><<<G_CONV, 128>>>();
    k_reduce<<<1, 256>>>(G_CONV, 1.f/(NPTS*12), gl2, tl2, 1);
    k_out<12><<<NPTS/32, 256>>>(out);
}